// round 11
// baseline (speedup 1.0000x reference)
#include <cuda_runtime.h>
#include <cuda_fp16.h>
#include <cstdint>

#define EN   1024
#define DFFN 4096
#define NB   2
#define LL   2048
#define HHH  16
#define ROWS (NB*LL)   // 4096
#define PMW  (NB*HHH*LL*LL/32)   // packed mask words: 4194304

// ---------------- scratch (device globals; no allocation allowed) ----------
__device__ __half g_hh   [ROWS*EN];
__device__ __half g_qkvh [ROWS*3*EN];
__device__ __half g_attnh[ROWS*EN];
__device__ float  g_x1   [ROWS*EN];
__device__ __half g_h2   [ROWS*EN];
__device__ __half g_ff   [ROWS*DFFN];
__device__ float  g_bqkv [3*EN];
__device__ unsigned g_pmask[PMW];
__device__ __half g_Wqkvt[3*EN*EN];
__device__ __half g_Wot  [EN*EN];
__device__ __half g_W1t  [DFFN*EN];
__device__ __half g_W2t  [EN*DFFN];

// ---------------- helpers ---------------------------------------------------
__device__ __forceinline__ unsigned pack_f16(float lo, float hi) {
    __half2 p = __floats2half2_rn(lo, hi);
    return *reinterpret_cast<unsigned*>(&p);
}
__device__ __forceinline__ void mma_f16(float* c, const unsigned* a, unsigned b0, unsigned b1) {
    asm volatile(
        "mma.sync.aligned.m16n8k16.row.col.f32.f16.f16.f32 "
        "{%0,%1,%2,%3},{%4,%5,%6,%7},{%8,%9},{%0,%1,%2,%3};"
        : "+f"(c[0]), "+f"(c[1]), "+f"(c[2]), "+f"(c[3])
        : "r"(a[0]), "r"(a[1]), "r"(a[2]), "r"(a[3]), "r"(b0), "r"(b1));
}
__device__ __forceinline__ void cpa16(unsigned dst, const void* src) {
    asm volatile("cp.async.cg.shared.global [%0], [%1], 16;\n" :: "r"(dst), "l"(src));
}
#define CP_COMMIT() asm volatile("cp.async.commit_group;\n" ::)
#define CP_WAIT0()  asm volatile("cp.async.wait_group 0;\n" ::)
#define CP_WAIT1()  asm volatile("cp.async.wait_group 1;\n" ::)

__device__ __forceinline__ uint32_t smem_u32(const void* p) {
    uint32_t a;
    asm("{ .reg .u64 t; cvta.to.shared.u64 t, %1; cvt.u32.u64 %0, t; }" : "=r"(a) : "l"(p));
    return a;
}
__device__ __forceinline__ void ldsm_x4(unsigned* r, uint32_t addr) {
    asm volatile("ldmatrix.sync.aligned.m8n8.x4.shared.b16 {%0,%1,%2,%3}, [%4];"
        : "=r"(r[0]), "=r"(r[1]), "=r"(r[2]), "=r"(r[3]) : "r"(addr));
}
__device__ __forceinline__ void ldsm_x4_t(unsigned* r, uint32_t addr) {
    asm volatile("ldmatrix.sync.aligned.m8n8.x4.trans.shared.b16 {%0,%1,%2,%3}, [%4];"
        : "=r"(r[0]), "=r"(r[1]), "=r"(r[2]), "=r"(r[3]) : "r"(addr));
}

__device__ __forceinline__ void blockReduce2(float& a, float& b) {
    __shared__ float sm[16];
    #pragma unroll
    for (int o = 16; o; o >>= 1) {
        a += __shfl_xor_sync(0xFFFFFFFFu, a, o);
        b += __shfl_xor_sync(0xFFFFFFFFu, b, o);
    }
    int w = threadIdx.x >> 5, lane = threadIdx.x & 31;
    __syncthreads();
    if (lane == 0) { sm[w] = a; sm[8 + w] = b; }
    __syncthreads();
    a = 0.f; b = 0.f;
    #pragma unroll
    for (int i = 0; i < 8; i++) { a += sm[i]; b += sm[8 + i]; }
}

// ---------------- mask bit-pack ----------------------------------------------
__global__ __launch_bounds__(256) void maskpack_k(const uint4* __restrict__ in,
                                                  unsigned* __restrict__ out) {
    int o = blockIdx.x * 256 + threadIdx.x;
    const uint4* p = in + (size_t)o * 8;
    unsigned m = 0;
    #pragma unroll
    for (int i = 0; i < 8; i++) {
        uint4 v = p[i];
        m |= (v.x ? 1u : 0u) << (i * 4 + 0);
        m |= (v.y ? 1u : 0u) << (i * 4 + 1);
        m |= (v.z ? 1u : 0u) << (i * 4 + 2);
        m |= (v.w ? 1u : 0u) << (i * 4 + 3);
    }
    out[o] = m;
}

// ---------------- pre-pass: transpose + fp16, vectorized ---------------------
// out[n][k] = f16(in[k][n] * (n<slim ? sc : 1)); 64x64 tiles, 256 threads.
// Loads: float4; stores: uint2 (4 halfs).
__global__ __launch_bounds__(256) void transT_f16_k(const float* __restrict__ in,
                                                    __half* __restrict__ out,
                                                    int K, int N, int slim, float sc) {
    __shared__ float tile[64][65];
    int k0 = blockIdx.y * 64, n0 = blockIdx.x * 64;
    int tx = threadIdx.x & 15, ty = threadIdx.x >> 4;   // (16, 16)
    #pragma unroll
    for (int i = 0; i < 4; i++) {
        float4 v = *reinterpret_cast<const float4*>(
            in + (size_t)(k0 + ty + i * 16) * N + n0 + tx * 4);
        tile[ty + i * 16][tx * 4 + 0] = v.x;
        tile[ty + i * 16][tx * 4 + 1] = v.y;
        tile[ty + i * 16][tx * 4 + 2] = v.z;
        tile[ty + i * 16][tx * 4 + 3] = v.w;
    }
    __syncthreads();
    #pragma unroll
    for (int i = 0; i < 4; i++) {
        int n = n0 + ty + i * 16;
        float m = (n < slim) ? sc : 1.f;
        float a = tile[tx * 4 + 0][ty + i * 16] * m;
        float b = tile[tx * 4 + 1][ty + i * 16] * m;
        float c = tile[tx * 4 + 2][ty + i * 16] * m;
        float d = tile[tx * 4 + 3][ty + i * 16] * m;
        uint2 pk;
        pk.x = pack_f16(a, b);
        pk.y = pack_f16(c, d);
        *reinterpret_cast<uint2*>(out + (size_t)n * K + k0 + tx * 4) = pk;
    }
}
__global__ __launch_bounds__(256) void scale_bias_k(const float* __restrict__ in,
                                                    float* __restrict__ out) {
    int i = blockIdx.x * 256 + threadIdx.x;
    out[i] = i < EN ? in[i] * 0.125f : in[i];
}

// ---------------- LN kernels -------------------------------------------------
__global__ __launch_bounds__(256) void ln1_k(const float* __restrict__ x,
                                             const float* __restrict__ s,
                                             const float* __restrict__ b,
                                             __half* __restrict__ out) {
    int row = blockIdx.x, t = threadIdx.x;
    float4 v = reinterpret_cast<const float4*>(x + (size_t)row * EN)[t];
    float sum = v.x + v.y + v.z + v.w;
    float sq  = v.x*v.x + v.y*v.y + v.z*v.z + v.w*v.w;
    blockReduce2(sum, sq);
    float mu = sum * (1.f / EN);
    float rs = rsqrtf(sq * (1.f / EN) - mu * mu + 1e-5f);
    float4 sv = reinterpret_cast<const float4*>(s)[t];
    float4 bv = reinterpret_cast<const float4*>(b)[t];
    uint2 pk;
    pk.x = pack_f16((v.x - mu) * rs * sv.x + bv.x, (v.y - mu) * rs * sv.y + bv.y);
    pk.y = pack_f16((v.z - mu) * rs * sv.z + bv.z, (v.w - mu) * rs * sv.w + bv.w);
    reinterpret_cast<uint2*>(out + (size_t)row * EN)[t] = pk;
}

__global__ __launch_bounds__(256) void ln2f_k(const float* __restrict__ x,
                                              const float* __restrict__ s2,
                                              const float* __restrict__ b2,
                                              const float* __restrict__ sf,
                                              const float* __restrict__ bf,
                                              __half* __restrict__ out) {
    int row = blockIdx.x, t = threadIdx.x;
    float4 v = reinterpret_cast<const float4*>(x + (size_t)row * EN)[t];
    float sum = v.x + v.y + v.z + v.w;
    float sq  = v.x*v.x + v.y*v.y + v.z*v.z + v.w*v.w;
    blockReduce2(sum, sq);
    float mu = sum * (1.f / EN);
    float rs = rsqrtf(sq * (1.f / EN) - mu * mu + 1e-5f);
    float4 sv = reinterpret_cast<const float4*>(s2)[t];
    float4 bv = reinterpret_cast<const float4*>(b2)[t];
    float4 y;
    y.x = (v.x - mu) * rs * sv.x + bv.x;
    y.y = (v.y - mu) * rs * sv.y + bv.y;
    y.z = (v.z - mu) * rs * sv.z + bv.z;
    y.w = (v.w - mu) * rs * sv.w + bv.w;
    float sum2 = y.x + y.y + y.z + y.w;
    float sq2  = y.x*y.x + y.y*y.y + y.z*y.z + y.w*y.w;
    blockReduce2(sum2, sq2);
    float mu2 = sum2 * (1.f / EN);
    float rs2 = rsqrtf(sq2 * (1.f / EN) - mu2 * mu2 + 1e-5f);
    float4 fv = reinterpret_cast<const float4*>(sf)[t];
    float4 gv = reinterpret_cast<const float4*>(bf)[t];
    uint2 pk;
    pk.x = pack_f16((y.x - mu2) * rs2 * fv.x + gv.x, (y.y - mu2) * rs2 * fv.y + gv.y);
    pk.y = pack_f16((y.z - mu2) * rs2 * fv.z + gv.z, (y.w - mu2) * rs2 * fv.w + gv.w);
    reinterpret_cast<uint2*>(out + (size_t)row * EN)[t] = pk;
}

// ---------------- fp16 GEMM (proven R7/R9 config: 128x128, 2 CTA/SM) ---------
#define EPI_BIAS 0
#define EPI_GELU 1
#define EPI_RES  2

#define STG_WORDS (2*128*48)
#define GEMM_SMEM (2*STG_WORDS*4)

template <int EPI, typename TO>
__global__ __launch_bounds__(128, 2) void gemm4_k(int M, int N, int K,
                                                  const __half* __restrict__ A,
                                                  const __half* __restrict__ Bt,
                                                  const float* __restrict__ bias,
                                                  const float* __restrict__ res,
                                                  TO* __restrict__ C) {
    extern __shared__ float smem[];
    constexpr int BKE = 64;
    int bm = blockIdx.y * 128, bn = blockIdx.x * 128;
    int t = threadIdx.x, wid = t >> 5, lane = t & 31;
    int g = lane >> 2, tg = lane & 3;
    int wr = (wid & 1) * 64;
    int wc = (wid >> 1) * 64;

    float c[4][8][4];
    #pragma unroll
    for (int mi = 0; mi < 4; mi++)
        #pragma unroll
        for (int nj = 0; nj < 8; nj++)
            #pragma unroll
            for (int q = 0; q < 4; q++) c[mi][nj][q] = 0.f;

    const __half* Ab = A  + (size_t)bm * K;
    const __half* Bb = Bt + (size_t)bn * K;
    int r8 = t >> 3, c8 = t & 7;

    auto prefetch = [&](int kt, int s) {
        float* dA = smem + s * STG_WORDS;
        float* dB = dA + 128 * 48;
        size_t kofs = (size_t)kt * BKE + c8 * 8;
        unsigned da = (unsigned)__cvta_generic_to_shared(dA + r8 * 48 + c8 * 4);
        unsigned db = (unsigned)__cvta_generic_to_shared(dB + r8 * 48 + c8 * 4);
        #pragma unroll
        for (int i = 0; i < 8; i++) {
            cpa16(da + i * 16 * 48 * 4, Ab + (size_t)(r8 + i * 16) * K + kofs);
            cpa16(db + i * 16 * 48 * 4, Bb + (size_t)(r8 + i * 16) * K + kofs);
        }
    };

    int Tn = K / BKE;
    prefetch(0, 0);
    CP_COMMIT();

    for (int kt = 0; kt < Tn; kt++) {
        int s = kt & 1;
        CP_WAIT0();
        __syncthreads();
        if (kt + 1 < Tn) { prefetch(kt + 1, s ^ 1); CP_COMMIT(); }

        const float* cA = smem + s * STG_WORDS;
        const float* cB = cA + 128 * 48;
        #pragma unroll
        for (int u = 0; u < 2; u++) {
            uint4 aF[8], bF[8];
            #pragma unroll
            for (int i = 0; i < 8; i++) {
                int r = wr + (i >> 1) * 16 + g + (i & 1) * 8;
                aF[i] = *reinterpret_cast<const uint4*>(cA + r * 48 + u * 16 + tg * 4);
            }
            #pragma unroll
            for (int nj = 0; nj < 8; nj++) {
                int cc = wc + nj * 8 + g;
                bF[nj] = *reinterpret_cast<const uint4*>(cB + cc * 48 + u * 16 + tg * 4);
            }
            #pragma unroll
            for (int mi = 0; mi < 4; mi++) {
                unsigned ae[4] = {aF[2*mi].x, aF[2*mi+1].x, aF[2*mi].y, aF[2*mi+1].y};
                unsigned ao[4] = {aF[2*mi].z, aF[2*mi+1].z, aF[2*mi].w, aF[2*mi+1].w};
                #pragma unroll
                for (int nj = 0; nj < 8; nj++) {
                    mma_f16(c[mi][nj], ae, bF[nj].x, bF[nj].y);
                    mma_f16(c[mi][nj], ao, bF[nj].z, bF[nj].w);
                }
            }
        }
    }

    #pragma unroll
    for (int mi = 0; mi < 4; mi++) {
        #pragma unroll
        for (int nj = 0; nj < 8; nj++) {
            int row = bm + wr + mi * 16 + g;
            int col = bn + wc + nj * 8 + tg * 2;
            float b0 = bias[col], b1 = bias[col + 1];
            float v0 = c[mi][nj][0] + b0, v1 = c[mi][nj][1] + b1;
            float v2 = c[mi][nj][2] + b0, v3 = c[mi][nj][3] + b1;
            if (EPI == EPI_GELU) {
                v0 = 0.5f * v0 * (1.f + erff(v0 * 0.70710678118f));
                v1 = 0.5f * v1 * (1.f + erff(v1 * 0.70710678118f));
                v2 = 0.5f * v2 * (1.f + erff(v2 * 0.70710678118f));
                v3 = 0.5f * v3 * (1.f + erff(v3 * 0.70710678118f));
            }
            if (EPI == EPI_RES) {
                float2 r0 = *reinterpret_cast<const float2*>(res + (size_t)row * N + col);
                float2 r1 = *reinterpret_cast<const float2*>(res + (size_t)(row + 8) * N + col);
                v0 += r0.x; v1 += r0.y; v2 += r1.x; v3 += r1.y;
            }
            if (sizeof(TO) == 4) {
                float* Cf = (float*)C;
                *reinterpret_cast<float2*>(Cf + (size_t)row * N + col)       = make_float2(v0, v1);
                *reinterpret_cast<float2*>(Cf + (size_t)(row + 8) * N + col) = make_float2(v2, v3);
            } else {
                __half* Ch = (__half*)C;
                *reinterpret_cast<unsigned*>(Ch + (size_t)row * N + col)       = pack_f16(v0, v1);
                *reinterpret_cast<unsigned*>(Ch + (size_t)(row + 8) * N + col) = pack_f16(v2, v3);
            }
        }
    }
}

// ---------------- fp16 flash attention with bit-packed mask ------------------
#define ATTN_SMEM ((9216 + 2*18432)*2)   // 92160 B

__global__ __launch_bounds__(256) void attn_k(const unsigned* __restrict__ pm,
                                              const __half* __restrict__ qkv) {
    extern __shared__ __half smh[];
    uint32_t base = smem_u32(smh);
    int t = threadIdx.x, w = t >> 5, lane = t & 31;
    int g = lane >> 2, tg = lane & 3;
    int qt = blockIdx.x, nh = blockIdx.y;
    int n = nh >> 4, h = nh & 15;
    size_t qrow0 = (size_t)n * LL + (size_t)qt * 128;
    int r8 = t >> 3, c8 = t & 7;

    #pragma unroll
    for (int i = 0; i < 4; i++) {
        int r = r8 + i * 32;
        cpa16(base + (r * 72 + c8 * 8) * 2,
              qkv + (qrow0 + r) * 3072 + h * 64 + c8 * 8);
    }
    auto prefetchKV = [&](int kt, int s) {
        uint32_t ko = 9216 + s * 18432, vo = ko + 9216;
        size_t rowb = ((size_t)n * LL + kt * 128 + r8) * 3072 + h * 64 + c8 * 8;
        #pragma unroll
        for (int i = 0; i < 4; i++) {
            cpa16(base + (ko + (r8 + i * 32) * 72 + c8 * 8) * 2,
                  qkv + rowb + (size_t)i * 32 * 3072 + 1024);
            cpa16(base + (vo + (r8 + i * 32) * 72 + c8 * 8) * 2,
                  qkv + rowb + (size_t)i * 32 * 3072 + 2048);
        }
    };
    prefetchKV(0, 0);
    CP_COMMIT();

    float O[8][4];
    #pragma unroll
    for (int nj = 0; nj < 8; nj++)
        #pragma unroll
        for (int q = 0; q < 4; q++) O[nj][q] = 0.f;
    float l0 = 0.f, l1 = 0.f;
    unsigned aQ[4][4];
    bool qLoaded = false;

    size_t mrow = (size_t)nh * LL + (size_t)qt * 128 + w * 16;
    const unsigned* pm0 = pm + (mrow + g)     * (LL / 32);
    const unsigned* pm1 = pm + (mrow + g + 8) * (LL / 32);
    int klrow = lane & 7, ktile = lane >> 3;
    int vkv = ((lane >> 3) & 1) * 8 + (lane & 7);
    int vd  = (lane >> 4) * 8;
    int sh0 = 2 * tg;

    for (int kt = 0; kt < 16; kt++) {
        int s = kt & 1;
        if (kt + 1 < 16) { prefetchKV(kt + 1, s ^ 1); CP_COMMIT(); CP_WAIT1(); }
        else             { CP_WAIT0(); }
        __syncthreads();
        uint4 m0 = *reinterpret_cast<const uint4*>(pm0 + kt * 4);
        uint4 m1 = *reinterpret_cast<const uint4*>(pm1 + kt * 4);
        if (!qLoaded) {
            qLoaded = true;
            #pragma unroll
            for (int tt = 0; tt < 4; tt++) {
                const __half* qp = smh + (w * 16 + g) * 72 + tt * 16 + 2 * tg;
                aQ[tt][0] = *reinterpret_cast<const unsigned*>(qp);
                aQ[tt][1] = *reinterpret_cast<const unsigned*>(qp + 8 * 72);
                aQ[tt][2] = *reinterpret_cast<const unsigned*>(qp + 8);
                aQ[tt][3] = *reinterpret_cast<const unsigned*>(qp + 8 * 72 + 8);
            }
        }
        uint32_t ko = 9216 + s * 18432, vo = ko + 9216;

        float sc[16][4];
        #pragma unroll
        for (int j = 0; j < 16; j++) {
            unsigned bq[2][4];
            uint32_t ka = base + ((j * 8 + klrow) * 72 + ktile * 8 + ko) * 2;
            ldsm_x4(bq[0], ka);
            ldsm_x4(bq[1], ka + 64);
            sc[j][0] = sc[j][1] = sc[j][2] = sc[j][3] = 0.f;
            #pragma unroll
            for (int tt = 0; tt < 4; tt++)
                mma_f16(sc[j], aQ[tt], bq[tt >> 1][(tt & 1) * 2], bq[tt >> 1][(tt & 1) * 2 + 1]);
        }

        #pragma unroll
        for (int j = 0; j < 16; j++) {
            unsigned w0 = (&m0.x)[j >> 2];
            unsigned w1 = (&m1.x)[j >> 2];
            int sh = (j & 3) * 8 + sh0;
            sc[j][0] = (w0 >> sh) & 1       ? 0.f : __expf(sc[j][0]);
            sc[j][1] = (w0 >> (sh + 1)) & 1 ? 0.f : __expf(sc[j][1]);
            sc[j][2] = (w1 >> sh) & 1       ? 0.f : __expf(sc[j][2]);
            sc[j][3] = (w1 >> (sh + 1)) & 1 ? 0.f : __expf(sc[j][3]);
            l0 += sc[j][0] + sc[j][1];
            l1 += sc[j][2] + sc[j][3];
        }

        #pragma unroll
        for (int tt = 0; tt < 8; tt++) {
            unsigned pa[4];
            pa[0] = pack_f16(sc[2*tt    ][0], sc[2*tt    ][1]);
            pa[1] = pack_f16(sc[2*tt    ][2], sc[2*tt    ][3]);
            pa[2] = pack_f16(sc[2*tt + 1][0], sc[2*tt + 1][1]);
            pa[3] = pack_f16(sc[2*tt + 1][2], sc[2*tt + 1][3]);
            uint32_t va = base + ((tt * 16 + vkv) * 72 + vd + vo) * 2;
            #pragma unroll
            for (int njp = 0; njp < 4; njp++) {
                unsigned bv[4];
                ldsm_x4_t(bv, va + njp * 32);
                mma_f16(O[2*njp    ], pa, bv[0], bv[1]);
                mma_f16(O[2*njp + 1], pa, bv[2], bv[3]);
            }
        }
        __syncthreads();
    }

    l0 += __shfl_xor_sync(0xFFFFFFFFu, l0, 1);
    l0 += __shfl_xor_sync(0xFFFFFFFFu, l0, 2);
    l1 += __shfl_xor_sync(0xFFFFFFFFu, l1, 1);
    l1 += __shfl_xor_sync(0xFFFFFFFFu, l1, 2);
    float r0 = 1.f / l0, r1 = 1.f / l1;
    size_t orow = qrow0 + w * 16 + g;
    #pragma unroll
    for (int nj = 0; nj < 8; nj++) {
        int col = h * 64 + nj * 8 + 2 * tg;
        *reinterpret_cast<unsigned*>(g_attnh + orow * EN + col) =
            pack_f16(O[nj][0] * r0, O[nj][1] * r0);
        *reinterpret_cast<unsigned*>(g_attnh + (orow + 8) * EN + col) =
            pack_f16(O[nj][2] * r1, O[nj][3] * r1);
    }
}

// ---------------- launch -----------------------------------------------------
extern "C" void kernel_launch(void* const* d_in, const int* in_sizes, int n_in,
                              void* d_out, int out_size) {
    const float* x     = (const float*)d_in[0];
    const uint4* mask4 = (const uint4*)d_in[1];
    const float* ln1_s = (const float*)d_in[2];
    const float* ln1_b = (const float*)d_in[3];
    const float* Wqkv  = (const float*)d_in[4];
    const float* bqkv  = (const float*)d_in[5];
    const float* Wo    = (const float*)d_in[6];
    const float* bo    = (const float*)d_in[7];
    const float* ln2_s = (const float*)d_in[8];
    const float* ln2_b = (const float*)d_in[9];
    const float* lnf_s = (const float*)d_in[10];
    const float* lnf_b = (const float*)d_in[11];
    const float* W1    = (const float*)d_in[12];
    const float* b1    = (const float*)d_in[13];
    const float* W2    = (const float*)d_in[14];
    const float* b2    = (const float*)d_in[15];
    float* out = (float*)d_out;

    __half *p_hh, *p_qkvh, *p_attnh, *p_h2, *p_ff, *p_Wqkvt, *p_Wot, *p_W1t, *p_W2t;
    float *p_x1, *p_bqkv;
    unsigned* p_pmask;
    cudaGetSymbolAddress((void**)&p_hh,    g_hh);
    cudaGetSymbolAddress((void**)&p_qkvh,  g_qkvh);
    cudaGetSymbolAddress((void**)&p_attnh, g_attnh);
    cudaGetSymbolAddress((void**)&p_x1,    g_x1);
    cudaGetSymbolAddress((void**)&p_h2,    g_h2);
    cudaGetSymbolAddress((void**)&p_ff,    g_ff);
    cudaGetSymbolAddress((void**)&p_bqkv,  g_bqkv);
    cudaGetSymbolAddress((void**)&p_pmask, g_pmask);
    cudaGetSymbolAddress((void**)&p_Wqkvt, g_Wqkvt);
    cudaGetSymbolAddress((void**)&p_Wot,   g_Wot);
    cudaGetSymbolAddress((void**)&p_W1t,   g_W1t);
    cudaGetSymbolAddress((void**)&p_W2t,   g_W2t);

    cudaFuncSetAttribute(gemm4_k<EPI_BIAS, __half>, cudaFuncAttributeMaxDynamicSharedMemorySize, GEMM_SMEM);
    cudaFuncSetAttribute(gemm4_k<EPI_RES,  float>,  cudaFuncAttributeMaxDynamicSharedMemorySize, GEMM_SMEM);
    cudaFuncSetAttribute(gemm4_k<EPI_GELU, __half>, cudaFuncAttributeMaxDynamicSharedMemorySize, GEMM_SMEM);
    cudaFuncSetAttribute(attn_k, cudaFuncAttributeMaxDynamicSharedMemorySize, ATTN_SMEM);

    static cudaStream_t s2 = nullptr;
    static cudaEvent_t evF = nullptr, evJ = nullptr;
    if (!s2) {
        cudaStreamCreateWithFlags(&s2, cudaStreamNonBlocking);
        cudaEventCreateWithFlags(&evF, cudaEventDisableTiming);
        cudaEventCreateWithFlags(&evJ, cudaEventDisableTiming);
    }

    dim3 tb(256);
    // fork: side stream packs the mask and transposes late-needed weights.
    cudaEventRecord(evF, 0);
    cudaStreamWaitEvent(s2, evF, 0);
    maskpack_k<<<PMW / 256, 256, 0, s2>>>(mask4, p_pmask);
    transT_f16_k<<<dim3(EN/64,   EN/64), tb, 0, s2>>>(Wo, p_Wot,  EN, EN,   0, 1.f);
    transT_f16_k<<<dim3(DFFN/64, EN/64), tb, 0, s2>>>(W1, p_W1t,  EN, DFFN, 0, 1.f);
    transT_f16_k<<<dim3(EN/64, DFFN/64), tb, 0, s2>>>(W2, p_W2t,  DFFN, EN, 0, 1.f);
    cudaEventRecord(evJ, s2);

    transT_f16_k<<<dim3(3*EN/64, EN/64), tb>>>(Wqkv, p_Wqkvt, EN, 3*EN, EN, 0.125f);
    scale_bias_k<<<3*EN/256, 256>>>(bqkv, p_bqkv);

    // 1. h = LN1(x) -> fp16
    ln1_k<<<ROWS, 256>>>(x, ln1_s, ln1_b, p_hh);
    // 2. qkv = h @ Wqkv + bqkv
    gemm4_k<EPI_BIAS, __half><<<dim3(3*EN/128, ROWS/128), 128, GEMM_SMEM>>>(
        ROWS, 3*EN, EN, p_hh, p_Wqkvt, p_bqkv, nullptr, p_qkvh);

    // join: packed mask + late weights ready
    cudaStreamWaitEvent(0, evJ, 0);
    // 3. attention
    attn_k<<<dim3(LL/128, NB*HHH), 256, ATTN_SMEM>>>(p_pmask, p_qkvh);
    // 4. x1 = x + attn @ Wo + bo
    gemm4_k<EPI_RES, float><<<dim3(EN/128, ROWS/128), 128, GEMM_SMEM>>>(
        ROWS, EN, EN, p_attnh, p_Wot, bo, x, p_x1);
    // 5. h2 = LNf(LN2(x1)) -> fp16
    ln2f_k<<<ROWS, 256>>>(p_x1, ln2_s, ln2_b, lnf_s, lnf_b, p_h2);
    // 6. ff = gelu(h2 @ W1 + b1)
    gemm4_k<EPI_GELU, __half><<<dim3(DFFN/128, ROWS/128), 128, GEMM_SMEM>>>(
        ROWS, DFFN, EN, p_h2, p_W1t, b1, nullptr, p_ff);
    // 7. out = x1 + ff @ W2 + b2
    gemm4_k<EPI_RES, float><<<dim3(EN/128, ROWS/128), 128, GEMM_SMEM>>>(
        ROWS, EN, DFFN, p_ff, p_W2t, b2, p_x1, out);
}

// round 12
// speedup vs baseline: 1.5298x; 1.5298x over previous
#include <cuda_runtime.h>
#include <cuda_fp16.h>
#include <cstdint>

#define EN   1024
#define DFFN 4096
#define NB   2
#define LL   2048
#define HHH  16
#define ROWS (NB*LL)   // 4096
#define PMW  (NB*HHH*LL*LL/32)   // packed mask words: 4194304

// ---------------- scratch (device globals; no allocation allowed) ----------
__device__ __half g_hh   [ROWS*EN];
__device__ __half g_qkvh [ROWS*3*EN];
__device__ __half g_attnh[ROWS*EN];
__device__ float  g_x1   [ROWS*EN];
__device__ __half g_h2   [ROWS*EN];
__device__ __half g_ff   [ROWS*DFFN];
__device__ float  g_bqkv [3*EN];
__device__ unsigned g_pmask[PMW];
__device__ __half g_Wqkvt[3*EN*EN];
__device__ __half g_Wot  [EN*EN];
__device__ __half g_W1t  [DFFN*EN];
__device__ __half g_W2t  [EN*DFFN];

// ---------------- helpers ---------------------------------------------------
__device__ __forceinline__ unsigned pack_f16(float lo, float hi) {
    __half2 p = __floats2half2_rn(lo, hi);
    return *reinterpret_cast<unsigned*>(&p);
}
__device__ __forceinline__ void mma_f16(float* c, const unsigned* a, unsigned b0, unsigned b1) {
    asm volatile(
        "mma.sync.aligned.m16n8k16.row.col.f32.f16.f16.f32 "
        "{%0,%1,%2,%3},{%4,%5,%6,%7},{%8,%9},{%0,%1,%2,%3};"
        : "+f"(c[0]), "+f"(c[1]), "+f"(c[2]), "+f"(c[3])
        : "r"(a[0]), "r"(a[1]), "r"(a[2]), "r"(a[3]), "r"(b0), "r"(b1));
}
__device__ __forceinline__ void cpa16(unsigned dst, const void* src) {
    asm volatile("cp.async.cg.shared.global [%0], [%1], 16;\n" :: "r"(dst), "l"(src));
}
#define CP_COMMIT() asm volatile("cp.async.commit_group;\n" ::)
#define CP_WAIT0()  asm volatile("cp.async.wait_group 0;\n" ::)
#define CP_WAIT1()  asm volatile("cp.async.wait_group 1;\n" ::)

__device__ __forceinline__ uint32_t smem_u32(const void* p) {
    uint32_t a;
    asm("{ .reg .u64 t; cvta.to.shared.u64 t, %1; cvt.u32.u64 %0, t; }" : "=r"(a) : "l"(p));
    return a;
}
__device__ __forceinline__ void ldsm_x4(unsigned* r, uint32_t addr) {
    asm volatile("ldmatrix.sync.aligned.m8n8.x4.shared.b16 {%0,%1,%2,%3}, [%4];"
        : "=r"(r[0]), "=r"(r[1]), "=r"(r[2]), "=r"(r[3]) : "r"(addr));
}
__device__ __forceinline__ void ldsm_x4_t(unsigned* r, uint32_t addr) {
    asm volatile("ldmatrix.sync.aligned.m8n8.x4.trans.shared.b16 {%0,%1,%2,%3}, [%4];"
        : "=r"(r[0]), "=r"(r[1]), "=r"(r[2]), "=r"(r[3]) : "r"(addr));
}

__device__ __forceinline__ void blockReduce2(float& a, float& b) {
    __shared__ float sm[16];
    #pragma unroll
    for (int o = 16; o; o >>= 1) {
        a += __shfl_xor_sync(0xFFFFFFFFu, a, o);
        b += __shfl_xor_sync(0xFFFFFFFFu, b, o);
    }
    int w = threadIdx.x >> 5, lane = threadIdx.x & 31;
    __syncthreads();
    if (lane == 0) { sm[w] = a; sm[8 + w] = b; }
    __syncthreads();
    a = 0.f; b = 0.f;
    #pragma unroll
    for (int i = 0; i < 8; i++) { a += sm[i]; b += sm[8 + i]; }
}

// ---------------- mask bit-pack ----------------------------------------------
__global__ __launch_bounds__(256) void maskpack_k(const uint4* __restrict__ in,
                                                  unsigned* __restrict__ out) {
    int o = blockIdx.x * 256 + threadIdx.x;
    const uint4* p = in + (size_t)o * 8;
    unsigned m = 0;
    #pragma unroll
    for (int i = 0; i < 8; i++) {
        uint4 v = p[i];
        m |= (v.x ? 1u : 0u) << (i * 4 + 0);
        m |= (v.y ? 1u : 0u) << (i * 4 + 1);
        m |= (v.z ? 1u : 0u) << (i * 4 + 2);
        m |= (v.w ? 1u : 0u) << (i * 4 + 3);
    }
    out[o] = m;
}

// ---------------- pre-pass kernels -------------------------------------------
__global__ __launch_bounds__(256) void transT_f16_k(const float* __restrict__ in,
                                                    __half* __restrict__ out,
                                                    int K, int N, int slim, float sc) {
    __shared__ float tile[64][65];
    int k0 = blockIdx.y * 64, n0 = blockIdx.x * 64;
    int tx = threadIdx.x & 63, ty = threadIdx.x >> 6;
    #pragma unroll
    for (int i = 0; i < 64; i += 4)
        tile[ty + i][tx] = in[(size_t)(k0 + ty + i) * N + n0 + tx];
    __syncthreads();
    #pragma unroll
    for (int i = 0; i < 64; i += 4) {
        int n = n0 + ty + i;
        float v = tile[tx][ty + i];
        out[(size_t)n * K + k0 + tx] = __float2half(n < slim ? v * sc : v);
    }
}
__global__ __launch_bounds__(256) void scale_bias_k(const float* __restrict__ in,
                                                    float* __restrict__ out) {
    int i = blockIdx.x * 256 + threadIdx.x;
    out[i] = i < EN ? in[i] * 0.125f : in[i];
}

// ---------------- LN kernels -------------------------------------------------
__global__ __launch_bounds__(256) void ln1_k(const float* __restrict__ x,
                                             const float* __restrict__ s,
                                             const float* __restrict__ b,
                                             __half* __restrict__ out) {
    int row = blockIdx.x, t = threadIdx.x;
    float4 v = reinterpret_cast<const float4*>(x + (size_t)row * EN)[t];
    float sum = v.x + v.y + v.z + v.w;
    float sq  = v.x*v.x + v.y*v.y + v.z*v.z + v.w*v.w;
    blockReduce2(sum, sq);
    float mu = sum * (1.f / EN);
    float rs = rsqrtf(sq * (1.f / EN) - mu * mu + 1e-5f);
    float4 sv = reinterpret_cast<const float4*>(s)[t];
    float4 bv = reinterpret_cast<const float4*>(b)[t];
    uint2 pk;
    pk.x = pack_f16((v.x - mu) * rs * sv.x + bv.x, (v.y - mu) * rs * sv.y + bv.y);
    pk.y = pack_f16((v.z - mu) * rs * sv.z + bv.z, (v.w - mu) * rs * sv.w + bv.w);
    reinterpret_cast<uint2*>(out + (size_t)row * EN)[t] = pk;
}

__global__ __launch_bounds__(256) void ln2f_k(const float* __restrict__ x,
                                              const float* __restrict__ s2,
                                              const float* __restrict__ b2,
                                              const float* __restrict__ sf,
                                              const float* __restrict__ bf,
                                              __half* __restrict__ out) {
    int row = blockIdx.x, t = threadIdx.x;
    float4 v = reinterpret_cast<const float4*>(x + (size_t)row * EN)[t];
    float sum = v.x + v.y + v.z + v.w;
    float sq  = v.x*v.x + v.y*v.y + v.z*v.z + v.w*v.w;
    blockReduce2(sum, sq);
    float mu = sum * (1.f / EN);
    float rs = rsqrtf(sq * (1.f / EN) - mu * mu + 1e-5f);
    float4 sv = reinterpret_cast<const float4*>(s2)[t];
    float4 bv = reinterpret_cast<const float4*>(b2)[t];
    float4 y;
    y.x = (v.x - mu) * rs * sv.x + bv.x;
    y.y = (v.y - mu) * rs * sv.y + bv.y;
    y.z = (v.z - mu) * rs * sv.z + bv.z;
    y.w = (v.w - mu) * rs * sv.w + bv.w;
    float sum2 = y.x + y.y + y.z + y.w;
    float sq2  = y.x*y.x + y.y*y.y + y.z*y.z + y.w*y.w;
    blockReduce2(sum2, sq2);
    float mu2 = sum2 * (1.f / EN);
    float rs2 = rsqrtf(sq2 * (1.f / EN) - mu2 * mu2 + 1e-5f);
    float4 fv = reinterpret_cast<const float4*>(sf)[t];
    float4 gv = reinterpret_cast<const float4*>(bf)[t];
    uint2 pk;
    pk.x = pack_f16((y.x - mu2) * rs2 * fv.x + gv.x, (y.y - mu2) * rs2 * fv.y + gv.y);
    pk.y = pack_f16((y.z - mu2) * rs2 * fv.z + gv.z, (y.w - mu2) * rs2 * fv.w + gv.w);
    reinterpret_cast<uint2*>(out + (size_t)row * EN)[t] = pk;
}

// ---------------- fp16 GEMM (proven 128x128, 2 CTA/SM) -----------------------
#define EPI_BIAS 0
#define EPI_GELU 1
#define EPI_RES  2

#define STG_WORDS (2*128*48)
#define GEMM_SMEM (2*STG_WORDS*4)

template <int EPI, typename TO>
__global__ __launch_bounds__(128, 2) void gemm4_k(int M, int N, int K,
                                                  const __half* __restrict__ A,
                                                  const __half* __restrict__ Bt,
                                                  const float* __restrict__ bias,
                                                  const float* __restrict__ res,
                                                  TO* __restrict__ C) {
    extern __shared__ float smem[];
    constexpr int BKE = 64;
    int bm = blockIdx.y * 128, bn = blockIdx.x * 128;
    int t = threadIdx.x, wid = t >> 5, lane = t & 31;
    int g = lane >> 2, tg = lane & 3;
    int wr = (wid & 1) * 64;
    int wc = (wid >> 1) * 64;

    float c[4][8][4];
    #pragma unroll
    for (int mi = 0; mi < 4; mi++)
        #pragma unroll
        for (int nj = 0; nj < 8; nj++)
            #pragma unroll
            for (int q = 0; q < 4; q++) c[mi][nj][q] = 0.f;

    const __half* Ab = A  + (size_t)bm * K;
    const __half* Bb = Bt + (size_t)bn * K;
    int r8 = t >> 3, c8 = t & 7;

    auto prefetch = [&](int kt, int s) {
        float* dA = smem + s * STG_WORDS;
        float* dB = dA + 128 * 48;
        size_t kofs = (size_t)kt * BKE + c8 * 8;
        unsigned da = (unsigned)__cvta_generic_to_shared(dA + r8 * 48 + c8 * 4);
        unsigned db = (unsigned)__cvta_generic_to_shared(dB + r8 * 48 + c8 * 4);
        #pragma unroll
        for (int i = 0; i < 8; i++) {
            cpa16(da + i * 16 * 48 * 4, Ab + (size_t)(r8 + i * 16) * K + kofs);
            cpa16(db + i * 16 * 48 * 4, Bb + (size_t)(r8 + i * 16) * K + kofs);
        }
    };

    int Tn = K / BKE;
    prefetch(0, 0);
    CP_COMMIT();

    for (int kt = 0; kt < Tn; kt++) {
        int s = kt & 1;
        CP_WAIT0();
        __syncthreads();
        if (kt + 1 < Tn) { prefetch(kt + 1, s ^ 1); CP_COMMIT(); }

        const float* cA = smem + s * STG_WORDS;
        const float* cB = cA + 128 * 48;
        #pragma unroll
        for (int u = 0; u < 2; u++) {
            uint4 aF[8], bF[8];
            #pragma unroll
            for (int i = 0; i < 8; i++) {
                int r = wr + (i >> 1) * 16 + g + (i & 1) * 8;
                aF[i] = *reinterpret_cast<const uint4*>(cA + r * 48 + u * 16 + tg * 4);
            }
            #pragma unroll
            for (int nj = 0; nj < 8; nj++) {
                int cc = wc + nj * 8 + g;
                bF[nj] = *reinterpret_cast<const uint4*>(cB + cc * 48 + u * 16 + tg * 4);
            }
            #pragma unroll
            for (int mi = 0; mi < 4; mi++) {
                unsigned ae[4] = {aF[2*mi].x, aF[2*mi+1].x, aF[2*mi].y, aF[2*mi+1].y};
                unsigned ao[4] = {aF[2*mi].z, aF[2*mi+1].z, aF[2*mi].w, aF[2*mi+1].w};
                #pragma unroll
                for (int nj = 0; nj < 8; nj++) {
                    mma_f16(c[mi][nj], ae, bF[nj].x, bF[nj].y);
                    mma_f16(c[mi][nj], ao, bF[nj].z, bF[nj].w);
                }
            }
        }
    }

    #pragma unroll
    for (int mi = 0; mi < 4; mi++) {
        #pragma unroll
        for (int nj = 0; nj < 8; nj++) {
            int row = bm + wr + mi * 16 + g;
            int col = bn + wc + nj * 8 + tg * 2;
            float b0 = bias[col], b1 = bias[col + 1];
            float v0 = c[mi][nj][0] + b0, v1 = c[mi][nj][1] + b1;
            float v2 = c[mi][nj][2] + b0, v3 = c[mi][nj][3] + b1;
            if (EPI == EPI_GELU) {
                v0 = 0.5f * v0 * (1.f + erff(v0 * 0.70710678118f));
                v1 = 0.5f * v1 * (1.f + erff(v1 * 0.70710678118f));
                v2 = 0.5f * v2 * (1.f + erff(v2 * 0.70710678118f));
                v3 = 0.5f * v3 * (1.f + erff(v3 * 0.70710678118f));
            }
            if (EPI == EPI_RES) {
                float2 r0 = *reinterpret_cast<const float2*>(res + (size_t)row * N + col);
                float2 r1 = *reinterpret_cast<const float2*>(res + (size_t)(row + 8) * N + col);
                v0 += r0.x; v1 += r0.y; v2 += r1.x; v3 += r1.y;
            }
            if (sizeof(TO) == 4) {
                float* Cf = (float*)C;
                *reinterpret_cast<float2*>(Cf + (size_t)row * N + col)       = make_float2(v0, v1);
                *reinterpret_cast<float2*>(Cf + (size_t)(row + 8) * N + col) = make_float2(v2, v3);
            } else {
                __half* Ch = (__half*)C;
                *reinterpret_cast<unsigned*>(Ch + (size_t)row * N + col)       = pack_f16(v0, v1);
                *reinterpret_cast<unsigned*>(Ch + (size_t)(row + 8) * N + col) = pack_f16(v2, v3);
            }
        }
    }
}

// ---------------- fp16 flash attention with bit-packed mask ------------------
#define ATTN_SMEM ((9216 + 2*18432)*2)   // 92160 B

__global__ __launch_bounds__(256) void attn_k(const unsigned* __restrict__ pm,
                                              const __half* __restrict__ qkv) {
    extern __shared__ __half smh[];
    uint32_t base = smem_u32(smh);
    int t = threadIdx.x, w = t >> 5, lane = t & 31;
    int g = lane >> 2, tg = lane & 3;
    int qt = blockIdx.x, nh = blockIdx.y;
    int n = nh >> 4, h = nh & 15;
    size_t qrow0 = (size_t)n * LL + (size_t)qt * 128;
    int r8 = t >> 3, c8 = t & 7;

    #pragma unroll
    for (int i = 0; i < 4; i++) {
        int r = r8 + i * 32;
        cpa16(base + (r * 72 + c8 * 8) * 2,
              qkv + (qrow0 + r) * 3072 + h * 64 + c8 * 8);
    }
    auto prefetchKV = [&](int kt, int s) {
        uint32_t ko = 9216 + s * 18432, vo = ko + 9216;
        size_t rowb = ((size_t)n * LL + kt * 128 + r8) * 3072 + h * 64 + c8 * 8;
        #pragma unroll
        for (int i = 0; i < 4; i++) {
            cpa16(base + (ko + (r8 + i * 32) * 72 + c8 * 8) * 2,
                  qkv + rowb + (size_t)i * 32 * 3072 + 1024);
            cpa16(base + (vo + (r8 + i * 32) * 72 + c8 * 8) * 2,
                  qkv + rowb + (size_t)i * 32 * 3072 + 2048);
        }
    };
    prefetchKV(0, 0);
    CP_COMMIT();

    float O[8][4];
    #pragma unroll
    for (int nj = 0; nj < 8; nj++)
        #pragma unroll
        for (int q = 0; q < 4; q++) O[nj][q] = 0.f;
    float l0 = 0.f, l1 = 0.f;
    unsigned aQ[4][4];
    bool qLoaded = false;

    size_t mrow = (size_t)nh * LL + (size_t)qt * 128 + w * 16;
    const unsigned* pm0 = pm + (mrow + g)     * (LL / 32);
    const unsigned* pm1 = pm + (mrow + g + 8) * (LL / 32);
    int klrow = lane & 7, ktile = lane >> 3;
    int vkv = ((lane >> 3) & 1) * 8 + (lane & 7);
    int vd  = (lane >> 4) * 8;
    int sh0 = 2 * tg;

    for (int kt = 0; kt < 16; kt++) {
        int s = kt & 1;
        if (kt + 1 < 16) { prefetchKV(kt + 1, s ^ 1); CP_COMMIT(); CP_WAIT1(); }
        else             { CP_WAIT0(); }
        __syncthreads();
        uint4 m0 = *reinterpret_cast<const uint4*>(pm0 + kt * 4);
        uint4 m1 = *reinterpret_cast<const uint4*>(pm1 + kt * 4);
        if (!qLoaded) {
            qLoaded = true;
            #pragma unroll
            for (int tt = 0; tt < 4; tt++) {
                const __half* qp = smh + (w * 16 + g) * 72 + tt * 16 + 2 * tg;
                aQ[tt][0] = *reinterpret_cast<const unsigned*>(qp);
                aQ[tt][1] = *reinterpret_cast<const unsigned*>(qp + 8 * 72);
                aQ[tt][2] = *reinterpret_cast<const unsigned*>(qp + 8);
                aQ[tt][3] = *reinterpret_cast<const unsigned*>(qp + 8 * 72 + 8);
            }
        }
        uint32_t ko = 9216 + s * 18432, vo = ko + 9216;

        float sc[16][4];
        #pragma unroll
        for (int j = 0; j < 16; j++) {
            unsigned bq[2][4];
            uint32_t ka = base + ((j * 8 + klrow) * 72 + ktile * 8 + ko) * 2;
            ldsm_x4(bq[0], ka);
            ldsm_x4(bq[1], ka + 64);
            sc[j][0] = sc[j][1] = sc[j][2] = sc[j][3] = 0.f;
            #pragma unroll
            for (int tt = 0; tt < 4; tt++)
                mma_f16(sc[j], aQ[tt], bq[tt >> 1][(tt & 1) * 2], bq[tt >> 1][(tt & 1) * 2 + 1]);
        }

        #pragma unroll
        for (int j = 0; j < 16; j++) {
            unsigned w0 = (&m0.x)[j >> 2];
            unsigned w1 = (&m1.x)[j >> 2];
            int sh = (j & 3) * 8 + sh0;
            sc[j][0] = (w0 >> sh) & 1       ? 0.f : __expf(sc[j][0]);
            sc[j][1] = (w0 >> (sh + 1)) & 1 ? 0.f : __expf(sc[j][1]);
            sc[j][2] = (w1 >> sh) & 1       ? 0.f : __expf(sc[j][2]);
            sc[j][3] = (w1 >> (sh + 1)) & 1 ? 0.f : __expf(sc[j][3]);
            l0 += sc[j][0] + sc[j][1];
            l1 += sc[j][2] + sc[j][3];
        }

        #pragma unroll
        for (int tt = 0; tt < 8; tt++) {
            unsigned pa[4];
            pa[0] = pack_f16(sc[2*tt    ][0], sc[2*tt    ][1]);
            pa[1] = pack_f16(sc[2*tt    ][2], sc[2*tt    ][3]);
            pa[2] = pack_f16(sc[2*tt + 1][0], sc[2*tt + 1][1]);
            pa[3] = pack_f16(sc[2*tt + 1][2], sc[2*tt + 1][3]);
            uint32_t va = base + ((tt * 16 + vkv) * 72 + vd + vo) * 2;
            #pragma unroll
            for (int njp = 0; njp < 4; njp++) {
                unsigned bv[4];
                ldsm_x4_t(bv, va + njp * 32);
                mma_f16(O[2*njp    ], pa, bv[0], bv[1]);
                mma_f16(O[2*njp + 1], pa, bv[2], bv[3]);
            }
        }
        __syncthreads();
    }

    l0 += __shfl_xor_sync(0xFFFFFFFFu, l0, 1);
    l0 += __shfl_xor_sync(0xFFFFFFFFu, l0, 2);
    l1 += __shfl_xor_sync(0xFFFFFFFFu, l1, 1);
    l1 += __shfl_xor_sync(0xFFFFFFFFu, l1, 2);
    float r0 = 1.f / l0, r1 = 1.f / l1;
    size_t orow = qrow0 + w * 16 + g;
    #pragma unroll
    for (int nj = 0; nj < 8; nj++) {
        int col = h * 64 + nj * 8 + 2 * tg;
        *reinterpret_cast<unsigned*>(g_attnh + orow * EN + col) =
            pack_f16(O[nj][0] * r0, O[nj][1] * r0);
        *reinterpret_cast<unsigned*>(g_attnh + (orow + 8) * EN + col) =
            pack_f16(O[nj][2] * r1, O[nj][3] * r1);
    }
}

// ---------------- launch -----------------------------------------------------
extern "C" void kernel_launch(void* const* d_in, const int* in_sizes, int n_in,
                              void* d_out, int out_size) {
    const float* x     = (const float*)d_in[0];
    const uint4* mask4 = (const uint4*)d_in[1];
    const float* ln1_s = (const float*)d_in[2];
    const float* ln1_b = (const float*)d_in[3];
    const float* Wqkv  = (const float*)d_in[4];
    const float* bqkv  = (const float*)d_in[5];
    const float* Wo    = (const float*)d_in[6];
    const float* bo    = (const float*)d_in[7];
    const float* ln2_s = (const float*)d_in[8];
    const float* ln2_b = (const float*)d_in[9];
    const float* lnf_s = (const float*)d_in[10];
    const float* lnf_b = (const float*)d_in[11];
    const float* W1    = (const float*)d_in[12];
    const float* b1    = (const float*)d_in[13];
    const float* W2    = (const float*)d_in[14];
    const float* b2    = (const float*)d_in[15];
    float* out = (float*)d_out;

    __half *p_hh, *p_qkvh, *p_attnh, *p_h2, *p_ff, *p_Wqkvt, *p_Wot, *p_W1t, *p_W2t;
    float *p_x1, *p_bqkv;
    unsigned* p_pmask;
    cudaGetSymbolAddress((void**)&p_hh,    g_hh);
    cudaGetSymbolAddress((void**)&p_qkvh,  g_qkvh);
    cudaGetSymbolAddress((void**)&p_attnh, g_attnh);
    cudaGetSymbolAddress((void**)&p_x1,    g_x1);
    cudaGetSymbolAddress((void**)&p_h2,    g_h2);
    cudaGetSymbolAddress((void**)&p_ff,    g_ff);
    cudaGetSymbolAddress((void**)&p_bqkv,  g_bqkv);
    cudaGetSymbolAddress((void**)&p_pmask, g_pmask);
    cudaGetSymbolAddress((void**)&p_Wqkvt, g_Wqkvt);
    cudaGetSymbolAddress((void**)&p_Wot,   g_Wot);
    cudaGetSymbolAddress((void**)&p_W1t,   g_W1t);
    cudaGetSymbolAddress((void**)&p_W2t,   g_W2t);

    cudaFuncSetAttribute(gemm4_k<EPI_BIAS, __half>, cudaFuncAttributeMaxDynamicSharedMemorySize, GEMM_SMEM);
    cudaFuncSetAttribute(gemm4_k<EPI_RES,  float>,  cudaFuncAttributeMaxDynamicSharedMemorySize, GEMM_SMEM);
    cudaFuncSetAttribute(gemm4_k<EPI_GELU, __half>, cudaFuncAttributeMaxDynamicSharedMemorySize, GEMM_SMEM);
    cudaFuncSetAttribute(attn_k, cudaFuncAttributeMaxDynamicSharedMemorySize, ATTN_SMEM);

    static cudaStream_t s2 = nullptr;
    static cudaEvent_t evF = nullptr, evJ = nullptr;
    if (!s2) {
        cudaStreamCreateWithFlags(&s2, cudaStreamNonBlocking);
        cudaEventCreateWithFlags(&evF, cudaEventDisableTiming);
        cudaEventCreateWithFlags(&evJ, cudaEventDisableTiming);
    }

    // fork: mask bit-pack runs on s2, overlapping transT/LN1/QKV GEMM
    cudaEventRecord(evF, 0);
    cudaStreamWaitEvent(s2, evF, 0);
    maskpack_k<<<PMW / 256, 256, 0, s2>>>(mask4, p_pmask);
    cudaEventRecord(evJ, s2);

    dim3 tb(256);
    transT_f16_k<<<dim3(3*EN/64, EN/64), tb>>>(Wqkv, p_Wqkvt, EN, 3*EN, EN, 0.125f);
    transT_f16_k<<<dim3(EN/64,   EN/64), tb>>>(Wo,   p_Wot,   EN, EN,   0, 1.f);
    transT_f16_k<<<dim3(DFFN/64, EN/64), tb>>>(W1,   p_W1t,   EN, DFFN, 0, 1.f);
    transT_f16_k<<<dim3(EN/64, DFFN/64), tb>>>(W2,   p_W2t,   DFFN, EN, 0, 1.f);
    scale_bias_k<<<3*EN/256, 256>>>(bqkv, p_bqkv);

    // 1. h = LN1(x) -> fp16
    ln1_k<<<ROWS, 256>>>(x, ln1_s, ln1_b, p_hh);
    // 2. qkv = h @ Wqkv + bqkv (fp16 out; q pre-scaled)
    gemm4_k<EPI_BIAS, __half><<<dim3(3*EN/128, ROWS/128), 128, GEMM_SMEM>>>(
        ROWS, 3*EN, EN, p_hh, p_Wqkvt, p_bqkv, nullptr, p_qkvh);

    // join: packed mask must be ready before attention
    cudaStreamWaitEvent(0, evJ, 0);
    // 3. attention
    attn_k<<<dim3(LL/128, NB*HHH), 256, ATTN_SMEM>>>(p_pmask, p_qkvh);
    // 4. x1 = x + attn @ Wo + bo
    gemm4_k<EPI_RES, float><<<dim3(EN/128, ROWS/128), 128, GEMM_SMEM>>>(
        ROWS, EN, EN, p_attnh, p_Wot, bo, x, p_x1);
    // 5. h2 = LNf(LN2(x1)) -> fp16
    ln2f_k<<<ROWS, 256>>>(p_x1, ln2_s, ln2_b, lnf_s, lnf_b, p_h2);
    // 6. ff = gelu(h2 @ W1 + b1)
    gemm4_k<EPI_GELU, __half><<<dim3(DFFN/128, ROWS/128), 128, GEMM_SMEM>>>(
        ROWS, DFFN, EN, p_h2, p_W1t, b1, nullptr, p_ff);
    // 7. out = x1 + ff @ W2 + b2
    gemm4_k<EPI_RES, float><<<dim3(EN/128, ROWS/128), 128, GEMM_SMEM>>>(
        ROWS, EN, DFFN, p_ff, p_W2t, b2, p_x1, out);
}

// round 14
// speedup vs baseline: 1.5827x; 1.0345x over previous
#include <cuda_runtime.h>
#include <cuda_fp16.h>
#include <cstdint>

#define EN   1024
#define DFFN 4096
#define NB   2
#define LL   2048
#define HHH  16
#define ROWS (NB*LL)   // 4096
#define PMW  (NB*HHH*LL*LL/32)   // packed mask words: 4194304
#define QSCALE 0.18033688011112042f   // log2(e) / 8

// ---------------- scratch (device globals; no allocation allowed) ----------
__device__ __half g_hh   [ROWS*EN];
__device__ __half g_qkvh [ROWS*3*EN];
__device__ __half g_attnh[ROWS*EN];
__device__ float  g_x1   [ROWS*EN];
__device__ __half g_h2   [ROWS*EN];
__device__ __half g_ff   [ROWS*DFFN];
__device__ float  g_bqkv [3*EN];
__device__ unsigned g_pmask[PMW];
__device__ __half g_Wqkvt[3*EN*EN];
__device__ __half g_Wot  [EN*EN];
__device__ __half g_W1t  [DFFN*EN];
__device__ __half g_W2t  [EN*DFFN];

// ---------------- helpers ---------------------------------------------------
__device__ __forceinline__ unsigned pack_f16(float lo, float hi) {
    __half2 p = __floats2half2_rn(lo, hi);
    return *reinterpret_cast<unsigned*>(&p);
}
__device__ __forceinline__ void mma_f16(float* c, const unsigned* a, unsigned b0, unsigned b1) {
    asm volatile(
        "mma.sync.aligned.m16n8k16.row.col.f32.f16.f16.f32 "
        "{%0,%1,%2,%3},{%4,%5,%6,%7},{%8,%9},{%0,%1,%2,%3};"
        : "+f"(c[0]), "+f"(c[1]), "+f"(c[2]), "+f"(c[3])
        : "r"(a[0]), "r"(a[1]), "r"(a[2]), "r"(a[3]), "r"(b0), "r"(b1));
}
__device__ __forceinline__ void cpa16(unsigned dst, const void* src) {
    asm volatile("cp.async.cg.shared.global [%0], [%1], 16;\n" :: "r"(dst), "l"(src));
}
#define CP_COMMIT() asm volatile("cp.async.commit_group;\n" ::)
#define CP_WAIT0()  asm volatile("cp.async.wait_group 0;\n" ::)
#define CP_WAIT1()  asm volatile("cp.async.wait_group 1;\n" ::)

__device__ __forceinline__ uint32_t smem_u32(const void* p) {
    uint32_t a;
    asm("{ .reg .u64 t; cvta.to.shared.u64 t, %1; cvt.u32.u64 %0, t; }" : "=r"(a) : "l"(p));
    return a;
}
__device__ __forceinline__ void ldsm_x4(unsigned* r, uint32_t addr) {
    asm volatile("ldmatrix.sync.aligned.m8n8.x4.shared.b16 {%0,%1,%2,%3}, [%4];"
        : "=r"(r[0]), "=r"(r[1]), "=r"(r[2]), "=r"(r[3]) : "r"(addr));
}
__device__ __forceinline__ void ldsm_x4_t(unsigned* r, uint32_t addr) {
    asm volatile("ldmatrix.sync.aligned.m8n8.x4.trans.shared.b16 {%0,%1,%2,%3}, [%4];"
        : "=r"(r[0]), "=r"(r[1]), "=r"(r[2]), "=r"(r[3]) : "r"(addr));
}
__device__ __forceinline__ unsigned ex2_f16x2(unsigned x) {
    unsigned r;
    asm("ex2.approx.f16x2 %0, %1;" : "=r"(r) : "r"(x));
    return r;
}

__device__ __forceinline__ void blockReduce2(float& a, float& b) {
    __shared__ float sm[16];
    #pragma unroll
    for (int o = 16; o; o >>= 1) {
        a += __shfl_xor_sync(0xFFFFFFFFu, a, o);
        b += __shfl_xor_sync(0xFFFFFFFFu, b, o);
    }
    int w = threadIdx.x >> 5, lane = threadIdx.x & 31;
    __syncthreads();
    if (lane == 0) { sm[w] = a; sm[8 + w] = b; }
    __syncthreads();
    a = 0.f; b = 0.f;
    #pragma unroll
    for (int i = 0; i < 8; i++) { a += sm[i]; b += sm[8 + i]; }
}

// ---------------- mask bit-pack ----------------------------------------------
__global__ __launch_bounds__(256) void maskpack_k(const uint4* __restrict__ in,
                                                  unsigned* __restrict__ out) {
    int o = blockIdx.x * 256 + threadIdx.x;
    const uint4* p = in + (size_t)o * 8;
    unsigned m = 0;
    #pragma unroll
    for (int i = 0; i < 8; i++) {
        uint4 v = p[i];
        m |= (v.x ? 1u : 0u) << (i * 4 + 0);
        m |= (v.y ? 1u : 0u) << (i * 4 + 1);
        m |= (v.z ? 1u : 0u) << (i * 4 + 2);
        m |= (v.w ? 1u : 0u) << (i * 4 + 3);
    }
    out[o] = m;
}

// ---------------- pre-pass kernels -------------------------------------------
__global__ __launch_bounds__(256) void transT_f16_k(const float* __restrict__ in,
                                                    __half* __restrict__ out,
                                                    int K, int N, int slim, float sc) {
    __shared__ float tile[64][65];
    int k0 = blockIdx.y * 64, n0 = blockIdx.x * 64;
    int tx = threadIdx.x & 63, ty = threadIdx.x >> 6;
    #pragma unroll
    for (int i = 0; i < 64; i += 4)
        tile[ty + i][tx] = in[(size_t)(k0 + ty + i) * N + n0 + tx];
    __syncthreads();
    #pragma unroll
    for (int i = 0; i < 64; i += 4) {
        int n = n0 + ty + i;
        float v = tile[tx][ty + i];
        out[(size_t)n * K + k0 + tx] = __float2half(n < slim ? v * sc : v);
    }
}
__global__ __launch_bounds__(256) void scale_bias_k(const float* __restrict__ in,
                                                    float* __restrict__ out) {
    int i = blockIdx.x * 256 + threadIdx.x;
    out[i] = i < EN ? in[i] * QSCALE : in[i];
}

// ---------------- LN kernels -------------------------------------------------
__global__ __launch_bounds__(256) void ln1_k(const float* __restrict__ x,
                                             const float* __restrict__ s,
                                             const float* __restrict__ b,
                                             __half* __restrict__ out) {
    int row = blockIdx.x, t = threadIdx.x;
    float4 v = reinterpret_cast<const float4*>(x + (size_t)row * EN)[t];
    float sum = v.x + v.y + v.z + v.w;
    float sq  = v.x*v.x + v.y*v.y + v.z*v.z + v.w*v.w;
    blockReduce2(sum, sq);
    float mu = sum * (1.f / EN);
    float rs = rsqrtf(sq * (1.f / EN) - mu * mu + 1e-5f);
    float4 sv = reinterpret_cast<const float4*>(s)[t];
    float4 bv = reinterpret_cast<const float4*>(b)[t];
    uint2 pk;
    pk.x = pack_f16((v.x - mu) * rs * sv.x + bv.x, (v.y - mu) * rs * sv.y + bv.y);
    pk.y = pack_f16((v.z - mu) * rs * sv.z + bv.z, (v.w - mu) * rs * sv.w + bv.w);
    reinterpret_cast<uint2*>(out + (size_t)row * EN)[t] = pk;
}

__global__ __launch_bounds__(256) void ln2f_k(const float* __restrict__ x,
                                              const float* __restrict__ s2,
                                              const float* __restrict__ b2,
                                              const float* __restrict__ sf,
                                              const float* __restrict__ bf,
                                              __half* __restrict__ out) {
    int row = blockIdx.x, t = threadIdx.x;
    float4 v = reinterpret_cast<const float4*>(x + (size_t)row * EN)[t];
    float sum = v.x + v.y + v.z + v.w;
    float sq  = v.x*v.x + v.y*v.y + v.z*v.z + v.w*v.w;
    blockReduce2(sum, sq);
    float mu = sum * (1.f / EN);
    float rs = rsqrtf(sq * (1.f / EN) - mu * mu + 1e-5f);
    float4 sv = reinterpret_cast<const float4*>(s2)[t];
    float4 bv = reinterpret_cast<const float4*>(b2)[t];
    float4 y;
    y.x = (v.x - mu) * rs * sv.x + bv.x;
    y.y = (v.y - mu) * rs * sv.y + bv.y;
    y.z = (v.z - mu) * rs * sv.z + bv.z;
    y.w = (v.w - mu) * rs * sv.w + bv.w;
    float sum2 = y.x + y.y + y.z + y.w;
    float sq2  = y.x*y.x + y.y*y.y + y.z*y.z + y.w*y.w;
    blockReduce2(sum2, sq2);
    float mu2 = sum2 * (1.f / EN);
    float rs2 = rsqrtf(sq2 * (1.f / EN) - mu2 * mu2 + 1e-5f);
    float4 fv = reinterpret_cast<const float4*>(sf)[t];
    float4 gv = reinterpret_cast<const float4*>(bf)[t];
    uint2 pk;
    pk.x = pack_f16((y.x - mu2) * rs2 * fv.x + gv.x, (y.y - mu2) * rs2 * fv.y + gv.y);
    pk.y = pack_f16((y.z - mu2) * rs2 * fv.z + gv.z, (y.w - mu2) * rs2 * fv.w + gv.w);
    reinterpret_cast<uint2*>(out + (size_t)row * EN)[t] = pk;
}

// ---------------- fp16 GEMM (proven 128x128, 2 CTA/SM) -----------------------
#define EPI_BIAS 0
#define EPI_GELU 1
#define EPI_RES  2

#define STG_WORDS (2*128*48)
#define GEMM_SMEM (2*STG_WORDS*4)

template <int EPI, typename TO>
__global__ __launch_bounds__(128, 2) void gemm4_k(int M, int N, int K,
                                                  const __half* __restrict__ A,
                                                  const __half* __restrict__ Bt,
                                                  const float* __restrict__ bias,
                                                  const float* __restrict__ res,
                                                  TO* __restrict__ C) {
    extern __shared__ float smem[];
    constexpr int BKE = 64;
    int bm = blockIdx.y * 128, bn = blockIdx.x * 128;
    int t = threadIdx.x, wid = t >> 5, lane = t & 31;
    int g = lane >> 2, tg = lane & 3;
    int wr = (wid & 1) * 64;
    int wc = (wid >> 1) * 64;

    float c[4][8][4];
    #pragma unroll
    for (int mi = 0; mi < 4; mi++)
        #pragma unroll
        for (int nj = 0; nj < 8; nj++)
            #pragma unroll
            for (int q = 0; q < 4; q++) c[mi][nj][q] = 0.f;

    const __half* Ab = A  + (size_t)bm * K;
    const __half* Bb = Bt + (size_t)bn * K;
    int r8 = t >> 3, c8 = t & 7;

    auto prefetch = [&](int kt, int s) {
        float* dA = smem + s * STG_WORDS;
        float* dB = dA + 128 * 48;
        size_t kofs = (size_t)kt * BKE + c8 * 8;
        unsigned da = (unsigned)__cvta_generic_to_shared(dA + r8 * 48 + c8 * 4);
        unsigned db = (unsigned)__cvta_generic_to_shared(dB + r8 * 48 + c8 * 4);
        #pragma unroll
        for (int i = 0; i < 8; i++) {
            cpa16(da + i * 16 * 48 * 4, Ab + (size_t)(r8 + i * 16) * K + kofs);
            cpa16(db + i * 16 * 48 * 4, Bb + (size_t)(r8 + i * 16) * K + kofs);
        }
    };

    int Tn = K / BKE;
    prefetch(0, 0);
    CP_COMMIT();

    for (int kt = 0; kt < Tn; kt++) {
        int s = kt & 1;
        CP_WAIT0();
        __syncthreads();
        if (kt + 1 < Tn) { prefetch(kt + 1, s ^ 1); CP_COMMIT(); }

        const float* cA = smem + s * STG_WORDS;
        const float* cB = cA + 128 * 48;
        #pragma unroll
        for (int u = 0; u < 2; u++) {
            uint4 aF[8], bF[8];
            #pragma unroll
            for (int i = 0; i < 8; i++) {
                int r = wr + (i >> 1) * 16 + g + (i & 1) * 8;
                aF[i] = *reinterpret_cast<const uint4*>(cA + r * 48 + u * 16 + tg * 4);
            }
            #pragma unroll
            for (int nj = 0; nj < 8; nj++) {
                int cc = wc + nj * 8 + g;
                bF[nj] = *reinterpret_cast<const uint4*>(cB + cc * 48 + u * 16 + tg * 4);
            }
            #pragma unroll
            for (int mi = 0; mi < 4; mi++) {
                unsigned ae[4] = {aF[2*mi].x, aF[2*mi+1].x, aF[2*mi].y, aF[2*mi+1].y};
                unsigned ao[4] = {aF[2*mi].z, aF[2*mi+1].z, aF[2*mi].w, aF[2*mi+1].w};
                #pragma unroll
                for (int nj = 0; nj < 8; nj++) {
                    mma_f16(c[mi][nj], ae, bF[nj].x, bF[nj].y);
                    mma_f16(c[mi][nj], ao, bF[nj].z, bF[nj].w);
                }
            }
        }
    }

    #pragma unroll
    for (int mi = 0; mi < 4; mi++) {
        #pragma unroll
        for (int nj = 0; nj < 8; nj++) {
            int row = bm + wr + mi * 16 + g;
            int col = bn + wc + nj * 8 + tg * 2;
            float b0 = bias[col], b1 = bias[col + 1];
            float v0 = c[mi][nj][0] + b0, v1 = c[mi][nj][1] + b1;
            float v2 = c[mi][nj][2] + b0, v3 = c[mi][nj][3] + b1;
            if (EPI == EPI_GELU) {
                v0 = 0.5f * v0 * (1.f + erff(v0 * 0.70710678118f));
                v1 = 0.5f * v1 * (1.f + erff(v1 * 0.70710678118f));
                v2 = 0.5f * v2 * (1.f + erff(v2 * 0.70710678118f));
                v3 = 0.5f * v3 * (1.f + erff(v3 * 0.70710678118f));
            }
            if (EPI == EPI_RES) {
                float2 r0 = *reinterpret_cast<const float2*>(res + (size_t)row * N + col);
                float2 r1 = *reinterpret_cast<const float2*>(res + (size_t)(row + 8) * N + col);
                v0 += r0.x; v1 += r0.y; v2 += r1.x; v3 += r1.y;
            }
            if (sizeof(TO) == 4) {
                float* Cf = (float*)C;
                *reinterpret_cast<float2*>(Cf + (size_t)row * N + col)       = make_float2(v0, v1);
                *reinterpret_cast<float2*>(Cf + (size_t)(row + 8) * N + col) = make_float2(v2, v3);
            } else {
                __half* Ch = (__half*)C;
                *reinterpret_cast<unsigned*>(Ch + (size_t)row * N + col)       = pack_f16(v0, v1);
                *reinterpret_cast<unsigned*>(Ch + (size_t)(row + 8) * N + col) = pack_f16(v2, v3);
            }
        }
    }
}

// ---------------- fp16 flash attention: packed ex2 softmax -------------------
// Scores arrive in log2 domain (log2e/8 folded into Wq/bq). p = 2^s via
// ex2.approx.f16x2 (2 values per MUFU op); mask by AND after ex2.
#define ATTN_SMEM ((9216 + 2*18432)*2)   // 92160 B

__global__ __launch_bounds__(256) void attn_k(const unsigned* __restrict__ pm,
                                              const __half* __restrict__ qkv) {
    extern __shared__ __half smh[];
    uint32_t base = smem_u32(smh);
    int t = threadIdx.x, w = t >> 5, lane = t & 31;
    int g = lane >> 2, tg = lane & 3;
    int qt = blockIdx.x, nh = blockIdx.y;
    int n = nh >> 4, h = nh & 15;
    size_t qrow0 = (size_t)n * LL + (size_t)qt * 128;
    int r8 = t >> 3, c8 = t & 7;

    #pragma unroll
    for (int i = 0; i < 4; i++) {
        int r = r8 + i * 32;
        cpa16(base + (r * 72 + c8 * 8) * 2,
              qkv + (qrow0 + r) * 3072 + h * 64 + c8 * 8);
    }
    auto prefetchKV = [&](int kt, int s) {
        uint32_t ko = 9216 + s * 18432, vo = ko + 9216;
        size_t rowb = ((size_t)n * LL + kt * 128 + r8) * 3072 + h * 64 + c8 * 8;
        #pragma unroll
        for (int i = 0; i < 4; i++) {
            cpa16(base + (ko + (r8 + i * 32) * 72 + c8 * 8) * 2,
                  qkv + rowb + (size_t)i * 32 * 3072 + 1024);
            cpa16(base + (vo + (r8 + i * 32) * 72 + c8 * 8) * 2,
                  qkv + rowb + (size_t)i * 32 * 3072 + 2048);
        }
    };
    prefetchKV(0, 0);
    CP_COMMIT();

    float O[8][4];
    #pragma unroll
    for (int nj = 0; nj < 8; nj++)
        #pragma unroll
        for (int q = 0; q < 4; q++) O[nj][q] = 0.f;
    float l0 = 0.f, l1 = 0.f;
    unsigned aQ[4][4];
    bool qLoaded = false;

    size_t mrow = (size_t)nh * LL + (size_t)qt * 128 + w * 16;
    const unsigned* pm0 = pm + (mrow + g)     * (LL / 32);
    const unsigned* pm1 = pm + (mrow + g + 8) * (LL / 32);
    int klrow = lane & 7, ktile = lane >> 3;
    int vkv = ((lane >> 3) & 1) * 8 + (lane & 7);
    int vd  = (lane >> 4) * 8;
    int sh0 = 2 * tg;

    for (int kt = 0; kt < 16; kt++) {
        int s = kt & 1;
        if (kt + 1 < 16) { prefetchKV(kt + 1, s ^ 1); CP_COMMIT(); CP_WAIT1(); }
        else             { CP_WAIT0(); }
        __syncthreads();
        uint4 m0 = *reinterpret_cast<const uint4*>(pm0 + kt * 4);
        uint4 m1 = *reinterpret_cast<const uint4*>(pm1 + kt * 4);
        if (!qLoaded) {
            qLoaded = true;
            #pragma unroll
            for (int tt = 0; tt < 4; tt++) {
                const __half* qp = smh + (w * 16 + g) * 72 + tt * 16 + 2 * tg;
                aQ[tt][0] = *reinterpret_cast<const unsigned*>(qp);
                aQ[tt][1] = *reinterpret_cast<const unsigned*>(qp + 8 * 72);
                aQ[tt][2] = *reinterpret_cast<const unsigned*>(qp + 8);
                aQ[tt][3] = *reinterpret_cast<const unsigned*>(qp + 8 * 72 + 8);
            }
        }
        uint32_t ko = 9216 + s * 18432, vo = ko + 9216;

        // S = Q K^T (log2 domain)
        float sc[16][4];
        #pragma unroll
        for (int j = 0; j < 16; j++) {
            unsigned bq[2][4];
            uint32_t ka = base + ((j * 8 + klrow) * 72 + ktile * 8 + ko) * 2;
            ldsm_x4(bq[0], ka);
            ldsm_x4(bq[1], ka + 64);
            sc[j][0] = sc[j][1] = sc[j][2] = sc[j][3] = 0.f;
            #pragma unroll
            for (int tt = 0; tt < 4; tt++)
                mma_f16(sc[j], aQ[tt], bq[tt >> 1][(tt & 1) * 2], bq[tt >> 1][(tt & 1) * 2 + 1]);
        }

        // p = 2^s in packed fp16; mask via AND; per-tile half2 row sums
        unsigned pp[16][2];
        __half2 hs0 = __float2half2_rn(0.f), hs1 = __float2half2_rn(0.f);
        #pragma unroll
        for (int j = 0; j < 16; j++) {
            unsigned w0 = (&m0.x)[j >> 2];
            unsigned w1 = (&m1.x)[j >> 2];
            int sh = (j & 3) * 8 + sh0;
            unsigned f0 = (w0 >> sh) & 3u;
            unsigned f1 = (w1 >> sh) & 3u;
            unsigned km0 = ((f0 & 1u) ? 0u : 0x0000FFFFu) | ((f0 & 2u) ? 0u : 0xFFFF0000u);
            unsigned km1 = ((f1 & 1u) ? 0u : 0x0000FFFFu) | ((f1 & 2u) ? 0u : 0xFFFF0000u);
            unsigned p0 = ex2_f16x2(pack_f16(sc[j][0], sc[j][1])) & km0;
            unsigned p1 = ex2_f16x2(pack_f16(sc[j][2], sc[j][3])) & km1;
            pp[j][0] = p0;
            pp[j][1] = p1;
            hs0 = __hadd2(hs0, *reinterpret_cast<__half2*>(&p0));
            hs1 = __hadd2(hs1, *reinterpret_cast<__half2*>(&p1));
        }
        l0 += __low2float(hs0) + __high2float(hs0);
        l1 += __low2float(hs1) + __high2float(hs1);

        // O += P @ V  (pp rows are the A-fragments directly)
        #pragma unroll
        for (int tt = 0; tt < 8; tt++) {
            uint32_t va = base + ((tt * 16 + vkv) * 72 + vd + vo) * 2;
            #pragma unroll
            for (int njp = 0; njp < 4; njp++) {
                unsigned bv[4];
                ldsm_x4_t(bv, va + njp * 32);
                mma_f16(O[2*njp    ], &pp[2*tt][0], bv[0], bv[1]);
                mma_f16(O[2*njp + 1], &pp[2*tt][0], bv[2], bv[3]);
            }
        }
        __syncthreads();
    }

    l0 += __shfl_xor_sync(0xFFFFFFFFu, l0, 1);
    l0 += __shfl_xor_sync(0xFFFFFFFFu, l0, 2);
    l1 += __shfl_xor_sync(0xFFFFFFFFu, l1, 1);
    l1 += __shfl_xor_sync(0xFFFFFFFFu, l1, 2);
    float r0 = 1.f / l0, r1 = 1.f / l1;
    size_t orow = qrow0 + w * 16 + g;
    #pragma unroll
    for (int nj = 0; nj < 8; nj++) {
        int col = h * 64 + nj * 8 + 2 * tg;
        *reinterpret_cast<unsigned*>(g_attnh + orow * EN + col) =
            pack_f16(O[nj][0] * r0, O[nj][1] * r0);
        *reinterpret_cast<unsigned*>(g_attnh + (orow + 8) * EN + col) =
            pack_f16(O[nj][2] * r1, O[nj][3] * r1);
    }
}

// ---------------- launch -----------------------------------------------------
extern "C" void kernel_launch(void* const* d_in, const int* in_sizes, int n_in,
                              void* d_out, int out_size) {
    const float* x     = (const float*)d_in[0];
    const uint4* mask4 = (const uint4*)d_in[1];
    const float* ln1_s = (const float*)d_in[2];
    const float* ln1_b = (const float*)d_in[3];
    const float* Wqkv  = (const float*)d_in[4];
    const float* bqkv  = (const float*)d_in[5];
    const float* Wo    = (const float*)d_in[6];
    const float* bo    = (const float*)d_in[7];
    const float* ln2_s = (const float*)d_in[8];
    const float* ln2_b = (const float*)d_in[9];
    const float* lnf_s = (const float*)d_in[10];
    const float* lnf_b = (const float*)d_in[11];
    const float* W1    = (const float*)d_in[12];
    const float* b1    = (const float*)d_in[13];
    const float* W2    = (const float*)d_in[14];
    const float* b2    = (const float*)d_in[15];
    float* out = (float*)d_out;

    __half *p_hh, *p_qkvh, *p_attnh, *p_h2, *p_ff, *p_Wqkvt, *p_Wot, *p_W1t, *p_W2t;
    float *p_x1, *p_bqkv;
    unsigned* p_pmask;
    cudaGetSymbolAddress((void**)&p_hh,    g_hh);
    cudaGetSymbolAddress((void**)&p_qkvh,  g_qkvh);
    cudaGetSymbolAddress((void**)&p_attnh, g_attnh);
    cudaGetSymbolAddress((void**)&p_x1,    g_x1);
    cudaGetSymbolAddress((void**)&p_h2,    g_h2);
    cudaGetSymbolAddress((void**)&p_ff,    g_ff);
    cudaGetSymbolAddress((void**)&p_bqkv,  g_bqkv);
    cudaGetSymbolAddress((void**)&p_pmask, g_pmask);
    cudaGetSymbolAddress((void**)&p_Wqkvt, g_Wqkvt);
    cudaGetSymbolAddress((void**)&p_Wot,   g_Wot);
    cudaGetSymbolAddress((void**)&p_W1t,   g_W1t);
    cudaGetSymbolAddress((void**)&p_W2t,   g_W2t);

    cudaFuncSetAttribute(gemm4_k<EPI_BIAS, __half>, cudaFuncAttributeMaxDynamicSharedMemorySize, GEMM_SMEM);
    cudaFuncSetAttribute(gemm4_k<EPI_RES,  float>,  cudaFuncAttributeMaxDynamicSharedMemorySize, GEMM_SMEM);
    cudaFuncSetAttribute(gemm4_k<EPI_GELU, __half>, cudaFuncAttributeMaxDynamicSharedMemorySize, GEMM_SMEM);
    cudaFuncSetAttribute(attn_k, cudaFuncAttributeMaxDynamicSharedMemorySize, ATTN_SMEM);

    static cudaStream_t s2 = nullptr;
    static cudaEvent_t evF = nullptr, evJ = nullptr;
    if (!s2) {
        cudaStreamCreateWithFlags(&s2, cudaStreamNonBlocking);
        cudaEventCreateWithFlags(&evF, cudaEventDisableTiming);
        cudaEventCreateWithFlags(&evJ, cudaEventDisableTiming);
    }

    // fork: mask bit-pack runs on s2, overlapping transT/LN1/QKV GEMM
    cudaEventRecord(evF, 0);
    cudaStreamWaitEvent(s2, evF, 0);
    maskpack_k<<<PMW / 256, 256, 0, s2>>>(mask4, p_pmask);
    cudaEventRecord(evJ, s2);

    dim3 tb(256);
    transT_f16_k<<<dim3(3*EN/64, EN/64), tb>>>(Wqkv, p_Wqkvt, EN, 3*EN, EN, QSCALE);
    transT_f16_k<<<dim3(EN/64,   EN/64), tb>>>(Wo,   p_Wot,   EN, EN,   0, 1.f);
    transT_f16_k<<<dim3(DFFN/64, EN/64), tb>>>(W1,   p_W1t,   EN, DFFN, 0, 1.f);
    transT_f16_k<<<dim3(EN/64, DFFN/64), tb>>>(W2,   p_W2t,   DFFN, EN, 0, 1.f);
    scale_bias_k<<<3*EN/256, 256>>>(bqkv, p_bqkv);

    // 1. h = LN1(x) -> fp16
    ln1_k<<<ROWS, 256>>>(x, ln1_s, ln1_b, p_hh);
    // 2. qkv = h @ Wqkv + bqkv (fp16 out; q pre-scaled to log2 domain)
    gemm4_k<EPI_BIAS, __half><<<dim3(3*EN/128, ROWS/128), 128, GEMM_SMEM>>>(
        ROWS, 3*EN, EN, p_hh, p_Wqkvt, p_bqkv, nullptr, p_qkvh);

    // join: packed mask must be ready before attention
    cudaStreamWaitEvent(0, evJ, 0);
    // 3. attention
    attn_k<<<dim3(LL/128, NB*HHH), 256, ATTN_SMEM>>>(p_pmask, p_qkvh);
    // 4. x1 = x + attn @ Wo + bo
    gemm4_k<EPI_RES, float><<<dim3(EN/128, ROWS/128), 128, GEMM_SMEM>>>(
        ROWS, EN, EN, p_attnh, p_Wot, bo, x, p_x1);
    // 5. h2 = LNf(LN2(x1)) -> fp16
    ln2f_k<<<ROWS, 256>>>(p_x1, ln2_s, ln2_b, lnf_s, lnf_b, p_h2);
    // 6. ff = gelu(h2 @ W1 + b1)
    gemm4_k<EPI_GELU, __half><<<dim3(DFFN/128, ROWS/128), 128, GEMM_SMEM>>>(
        ROWS, DFFN, EN, p_h2, p_W1t, b1, nullptr, p_ff);
    // 7. out = x1 + ff @ W2 + b2
    gemm4_k<EPI_RES, float><<<dim3(EN/128, ROWS/128), 128, GEMM_SMEM>>>(
        ROWS, EN, DFFN, p_ff, p_W2t, b2, p_x1, out);
}

// round 15
// speedup vs baseline: 1.6423x; 1.0377x over previous
#include <cuda_runtime.h>
#include <cuda_fp16.h>
#include <cstdint>

#define EN   1024
#define DFFN 4096
#define NB   2
#define LL   2048
#define HHH  16
#define ROWS (NB*LL)   // 4096
#define PMW  (NB*HHH*LL*LL/32)   // packed mask words: 4194304
#define QSCALE 0.18033688011112042f   // log2(e) / 8

// ---------------- scratch (device globals; no allocation allowed) ----------
__device__ __half g_hh   [ROWS*EN];
__device__ __half g_qkvh [ROWS*3*EN];
__device__ __half g_attnh[ROWS*EN];
__device__ float  g_x1   [ROWS*EN];
__device__ __half g_h2   [ROWS*EN];
__device__ __half g_ff   [ROWS*DFFN];
__device__ float  g_bqkv [3*EN];
__device__ unsigned g_pmask[PMW];
__device__ __half g_Wqkvt[3*EN*EN];
__device__ __half g_Wot  [EN*EN];
__device__ __half g_W1t  [DFFN*EN];
__device__ __half g_W2t  [EN*DFFN];

// ---------------- helpers ---------------------------------------------------
__device__ __forceinline__ unsigned pack_f16(float lo, float hi) {
    __half2 p = __floats2half2_rn(lo, hi);
    return *reinterpret_cast<unsigned*>(&p);
}
__device__ __forceinline__ void mma_f16(float* c, const unsigned* a, unsigned b0, unsigned b1) {
    asm volatile(
        "mma.sync.aligned.m16n8k16.row.col.f32.f16.f16.f32 "
        "{%0,%1,%2,%3},{%4,%5,%6,%7},{%8,%9},{%0,%1,%2,%3};"
        : "+f"(c[0]), "+f"(c[1]), "+f"(c[2]), "+f"(c[3])
        : "r"(a[0]), "r"(a[1]), "r"(a[2]), "r"(a[3]), "r"(b0), "r"(b1));
}
// fp16-accumulate variant: C is 2 regs (packed half2 per 8-row group)
__device__ __forceinline__ void mma_f16h(unsigned* c, const unsigned* a, unsigned b0, unsigned b1) {
    asm volatile(
        "mma.sync.aligned.m16n8k16.row.col.f16.f16.f16.f16 "
        "{%0,%1},{%2,%3,%4,%5},{%6,%7},{%0,%1};"
        : "+r"(c[0]), "+r"(c[1])
        : "r"(a[0]), "r"(a[1]), "r"(a[2]), "r"(a[3]), "r"(b0), "r"(b1));
}
__device__ __forceinline__ void cpa16(unsigned dst, const void* src) {
    asm volatile("cp.async.cg.shared.global [%0], [%1], 16;\n" :: "r"(dst), "l"(src));
}
#define CP_COMMIT() asm volatile("cp.async.commit_group;\n" ::)
#define CP_WAIT0()  asm volatile("cp.async.wait_group 0;\n" ::)
#define CP_WAIT1()  asm volatile("cp.async.wait_group 1;\n" ::)

__device__ __forceinline__ uint32_t smem_u32(const void* p) {
    uint32_t a;
    asm("{ .reg .u64 t; cvta.to.shared.u64 t, %1; cvt.u32.u64 %0, t; }" : "=r"(a) : "l"(p));
    return a;
}
__device__ __forceinline__ void ldsm_x4(unsigned* r, uint32_t addr) {
    asm volatile("ldmatrix.sync.aligned.m8n8.x4.shared.b16 {%0,%1,%2,%3}, [%4];"
        : "=r"(r[0]), "=r"(r[1]), "=r"(r[2]), "=r"(r[3]) : "r"(addr));
}
__device__ __forceinline__ void ldsm_x4_t(unsigned* r, uint32_t addr) {
    asm volatile("ldmatrix.sync.aligned.m8n8.x4.trans.shared.b16 {%0,%1,%2,%3}, [%4];"
        : "=r"(r[0]), "=r"(r[1]), "=r"(r[2]), "=r"(r[3]) : "r"(addr));
}
__device__ __forceinline__ unsigned ex2_f16x2(unsigned x) {
    unsigned r;
    asm("ex2.approx.f16x2 %0, %1;" : "=r"(r) : "r"(x));
    return r;
}

__device__ __forceinline__ void blockReduce2(float& a, float& b) {
    __shared__ float sm[16];
    #pragma unroll
    for (int o = 16; o; o >>= 1) {
        a += __shfl_xor_sync(0xFFFFFFFFu, a, o);
        b += __shfl_xor_sync(0xFFFFFFFFu, b, o);
    }
    int w = threadIdx.x >> 5, lane = threadIdx.x & 31;
    __syncthreads();
    if (lane == 0) { sm[w] = a; sm[8 + w] = b; }
    __syncthreads();
    a = 0.f; b = 0.f;
    #pragma unroll
    for (int i = 0; i < 8; i++) { a += sm[i]; b += sm[8 + i]; }
}

// ---------------- mask bit-pack ----------------------------------------------
__global__ __launch_bounds__(256) void maskpack_k(const uint4* __restrict__ in,
                                                  unsigned* __restrict__ out) {
    int o = blockIdx.x * 256 + threadIdx.x;
    const uint4* p = in + (size_t)o * 8;
    unsigned m = 0;
    #pragma unroll
    for (int i = 0; i < 8; i++) {
        uint4 v = p[i];
        m |= (v.x ? 1u : 0u) << (i * 4 + 0);
        m |= (v.y ? 1u : 0u) << (i * 4 + 1);
        m |= (v.z ? 1u : 0u) << (i * 4 + 2);
        m |= (v.w ? 1u : 0u) << (i * 4 + 3);
    }
    out[o] = m;
}

// ---------------- pre-pass kernels -------------------------------------------
__global__ __launch_bounds__(256) void transT_f16_k(const float* __restrict__ in,
                                                    __half* __restrict__ out,
                                                    int K, int N, int slim, float sc) {
    __shared__ float tile[64][65];
    int k0 = blockIdx.y * 64, n0 = blockIdx.x * 64;
    int tx = threadIdx.x & 63, ty = threadIdx.x >> 6;
    #pragma unroll
    for (int i = 0; i < 64; i += 4)
        tile[ty + i][tx] = in[(size_t)(k0 + ty + i) * N + n0 + tx];
    __syncthreads();
    #pragma unroll
    for (int i = 0; i < 64; i += 4) {
        int n = n0 + ty + i;
        float v = tile[tx][ty + i];
        out[(size_t)n * K + k0 + tx] = __float2half(n < slim ? v * sc : v);
    }
}
__global__ __launch_bounds__(256) void scale_bias_k(const float* __restrict__ in,
                                                    float* __restrict__ out) {
    int i = blockIdx.x * 256 + threadIdx.x;
    out[i] = i < EN ? in[i] * QSCALE : in[i];
}

// ---------------- LN kernels -------------------------------------------------
__global__ __launch_bounds__(256) void ln1_k(const float* __restrict__ x,
                                             const float* __restrict__ s,
                                             const float* __restrict__ b,
                                             __half* __restrict__ out) {
    int row = blockIdx.x, t = threadIdx.x;
    float4 v = reinterpret_cast<const float4*>(x + (size_t)row * EN)[t];
    float sum = v.x + v.y + v.z + v.w;
    float sq  = v.x*v.x + v.y*v.y + v.z*v.z + v.w*v.w;
    blockReduce2(sum, sq);
    float mu = sum * (1.f / EN);
    float rs = rsqrtf(sq * (1.f / EN) - mu * mu + 1e-5f);
    float4 sv = reinterpret_cast<const float4*>(s)[t];
    float4 bv = reinterpret_cast<const float4*>(b)[t];
    uint2 pk;
    pk.x = pack_f16((v.x - mu) * rs * sv.x + bv.x, (v.y - mu) * rs * sv.y + bv.y);
    pk.y = pack_f16((v.z - mu) * rs * sv.z + bv.z, (v.w - mu) * rs * sv.w + bv.w);
    reinterpret_cast<uint2*>(out + (size_t)row * EN)[t] = pk;
}

__global__ __launch_bounds__(256) void ln2f_k(const float* __restrict__ x,
                                              const float* __restrict__ s2,
                                              const float* __restrict__ b2,
                                              const float* __restrict__ sf,
                                              const float* __restrict__ bf,
                                              __half* __restrict__ out) {
    int row = blockIdx.x, t = threadIdx.x;
    float4 v = reinterpret_cast<const float4*>(x + (size_t)row * EN)[t];
    float sum = v.x + v.y + v.z + v.w;
    float sq  = v.x*v.x + v.y*v.y + v.z*v.z + v.w*v.w;
    blockReduce2(sum, sq);
    float mu = sum * (1.f / EN);
    float rs = rsqrtf(sq * (1.f / EN) - mu * mu + 1e-5f);
    float4 sv = reinterpret_cast<const float4*>(s2)[t];
    float4 bv = reinterpret_cast<const float4*>(b2)[t];
    float4 y;
    y.x = (v.x - mu) * rs * sv.x + bv.x;
    y.y = (v.y - mu) * rs * sv.y + bv.y;
    y.z = (v.z - mu) * rs * sv.z + bv.z;
    y.w = (v.w - mu) * rs * sv.w + bv.w;
    float sum2 = y.x + y.y + y.z + y.w;
    float sq2  = y.x*y.x + y.y*y.y + y.z*y.z + y.w*y.w;
    blockReduce2(sum2, sq2);
    float mu2 = sum2 * (1.f / EN);
    float rs2 = rsqrtf(sq2 * (1.f / EN) - mu2 * mu2 + 1e-5f);
    float4 fv = reinterpret_cast<const float4*>(sf)[t];
    float4 gv = reinterpret_cast<const float4*>(bf)[t];
    uint2 pk;
    pk.x = pack_f16((y.x - mu2) * rs2 * fv.x + gv.x, (y.y - mu2) * rs2 * fv.y + gv.y);
    pk.y = pack_f16((y.z - mu2) * rs2 * fv.z + gv.z, (y.w - mu2) * rs2 * fv.w + gv.w);
    reinterpret_cast<uint2*>(out + (size_t)row * EN)[t] = pk;
}

// ---------------- fp16 GEMM (proven 128x128, 2 CTA/SM) -----------------------
#define EPI_BIAS 0
#define EPI_GELU 1
#define EPI_RES  2

#define STG_WORDS (2*128*48)
#define GEMM_SMEM (2*STG_WORDS*4)

template <int EPI, typename TO>
__global__ __launch_bounds__(128, 2) void gemm4_k(int M, int N, int K,
                                                  const __half* __restrict__ A,
                                                  const __half* __restrict__ Bt,
                                                  const float* __restrict__ bias,
                                                  const float* __restrict__ res,
                                                  TO* __restrict__ C) {
    extern __shared__ float smem[];
    constexpr int BKE = 64;
    int bm = blockIdx.y * 128, bn = blockIdx.x * 128;
    int t = threadIdx.x, wid = t >> 5, lane = t & 31;
    int g = lane >> 2, tg = lane & 3;
    int wr = (wid & 1) * 64;
    int wc = (wid >> 1) * 64;

    float c[4][8][4];
    #pragma unroll
    for (int mi = 0; mi < 4; mi++)
        #pragma unroll
        for (int nj = 0; nj < 8; nj++)
            #pragma unroll
            for (int q = 0; q < 4; q++) c[mi][nj][q] = 0.f;

    const __half* Ab = A  + (size_t)bm * K;
    const __half* Bb = Bt + (size_t)bn * K;
    int r8 = t >> 3, c8 = t & 7;

    auto prefetch = [&](int kt, int s) {
        float* dA = smem + s * STG_WORDS;
        float* dB = dA + 128 * 48;
        size_t kofs = (size_t)kt * BKE + c8 * 8;
        unsigned da = (unsigned)__cvta_generic_to_shared(dA + r8 * 48 + c8 * 4);
        unsigned db = (unsigned)__cvta_generic_to_shared(dB + r8 * 48 + c8 * 4);
        #pragma unroll
        for (int i = 0; i < 8; i++) {
            cpa16(da + i * 16 * 48 * 4, Ab + (size_t)(r8 + i * 16) * K + kofs);
            cpa16(db + i * 16 * 48 * 4, Bb + (size_t)(r8 + i * 16) * K + kofs);
        }
    };

    int Tn = K / BKE;
    prefetch(0, 0);
    CP_COMMIT();

    for (int kt = 0; kt < Tn; kt++) {
        int s = kt & 1;
        CP_WAIT0();
        __syncthreads();
        if (kt + 1 < Tn) { prefetch(kt + 1, s ^ 1); CP_COMMIT(); }

        const float* cA = smem + s * STG_WORDS;
        const float* cB = cA + 128 * 48;
        #pragma unroll
        for (int u = 0; u < 2; u++) {
            uint4 aF[8], bF[8];
            #pragma unroll
            for (int i = 0; i < 8; i++) {
                int r = wr + (i >> 1) * 16 + g + (i & 1) * 8;
                aF[i] = *reinterpret_cast<const uint4*>(cA + r * 48 + u * 16 + tg * 4);
            }
            #pragma unroll
            for (int nj = 0; nj < 8; nj++) {
                int cc = wc + nj * 8 + g;
                bF[nj] = *reinterpret_cast<const uint4*>(cB + cc * 48 + u * 16 + tg * 4);
            }
            #pragma unroll
            for (int mi = 0; mi < 4; mi++) {
                unsigned ae[4] = {aF[2*mi].x, aF[2*mi+1].x, aF[2*mi].y, aF[2*mi+1].y};
                unsigned ao[4] = {aF[2*mi].z, aF[2*mi+1].z, aF[2*mi].w, aF[2*mi+1].w};
                #pragma unroll
                for (int nj = 0; nj < 8; nj++) {
                    mma_f16(c[mi][nj], ae, bF[nj].x, bF[nj].y);
                    mma_f16(c[mi][nj], ao, bF[nj].z, bF[nj].w);
                }
            }
        }
    }

    #pragma unroll
    for (int mi = 0; mi < 4; mi++) {
        #pragma unroll
        for (int nj = 0; nj < 8; nj++) {
            int row = bm + wr + mi * 16 + g;
            int col = bn + wc + nj * 8 + tg * 2;
            float b0 = bias[col], b1 = bias[col + 1];
            float v0 = c[mi][nj][0] + b0, v1 = c[mi][nj][1] + b1;
            float v2 = c[mi][nj][2] + b0, v3 = c[mi][nj][3] + b1;
            if (EPI == EPI_GELU) {
                v0 = 0.5f * v0 * (1.f + erff(v0 * 0.70710678118f));
                v1 = 0.5f * v1 * (1.f + erff(v1 * 0.70710678118f));
                v2 = 0.5f * v2 * (1.f + erff(v2 * 0.70710678118f));
                v3 = 0.5f * v3 * (1.f + erff(v3 * 0.70710678118f));
            }
            if (EPI == EPI_RES) {
                float2 r0 = *reinterpret_cast<const float2*>(res + (size_t)row * N + col);
                float2 r1 = *reinterpret_cast<const float2*>(res + (size_t)(row + 8) * N + col);
                v0 += r0.x; v1 += r0.y; v2 += r1.x; v3 += r1.y;
            }
            if (sizeof(TO) == 4) {
                float* Cf = (float*)C;
                *reinterpret_cast<float2*>(Cf + (size_t)row * N + col)       = make_float2(v0, v1);
                *reinterpret_cast<float2*>(Cf + (size_t)(row + 8) * N + col) = make_float2(v2, v3);
            } else {
                __half* Ch = (__half*)C;
                *reinterpret_cast<unsigned*>(Ch + (size_t)row * N + col)       = pack_f16(v0, v1);
                *reinterpret_cast<unsigned*>(Ch + (size_t)(row + 8) * N + col) = pack_f16(v2, v3);
            }
        }
    }
}

// ---------------- fp16 flash attention: fp16-accum MMA + packed ex2 ----------
// Scores in log2 domain; S and O accumulate in fp16 (C-frag = packed half2,
// which IS the softmax/PV layout). Row sums in fp32 across tiles.
#define ATTN_SMEM ((9216 + 2*18432)*2)   // 92160 B

__global__ __launch_bounds__(256) void attn_k(const unsigned* __restrict__ pm,
                                              const __half* __restrict__ qkv) {
    extern __shared__ __half smh[];
    uint32_t base = smem_u32(smh);
    int t = threadIdx.x, w = t >> 5, lane = t & 31;
    int g = lane >> 2, tg = lane & 3;
    int qt = blockIdx.x, nh = blockIdx.y;
    int n = nh >> 4, h = nh & 15;
    size_t qrow0 = (size_t)n * LL + (size_t)qt * 128;
    int r8 = t >> 3, c8 = t & 7;

    #pragma unroll
    for (int i = 0; i < 4; i++) {
        int r = r8 + i * 32;
        cpa16(base + (r * 72 + c8 * 8) * 2,
              qkv + (qrow0 + r) * 3072 + h * 64 + c8 * 8);
    }
    auto prefetchKV = [&](int kt, int s) {
        uint32_t ko = 9216 + s * 18432, vo = ko + 9216;
        size_t rowb = ((size_t)n * LL + kt * 128 + r8) * 3072 + h * 64 + c8 * 8;
        #pragma unroll
        for (int i = 0; i < 4; i++) {
            cpa16(base + (ko + (r8 + i * 32) * 72 + c8 * 8) * 2,
                  qkv + rowb + (size_t)i * 32 * 3072 + 1024);
            cpa16(base + (vo + (r8 + i * 32) * 72 + c8 * 8) * 2,
                  qkv + rowb + (size_t)i * 32 * 3072 + 2048);
        }
    };
    prefetchKV(0, 0);
    CP_COMMIT();

    unsigned O[8][2];        // fp16-accum C-frags
    #pragma unroll
    for (int nj = 0; nj < 8; nj++) { O[nj][0] = 0u; O[nj][1] = 0u; }
    float l0 = 0.f, l1 = 0.f;
    unsigned aQ[4][4];
    bool qLoaded = false;

    size_t mrow = (size_t)nh * LL + (size_t)qt * 128 + w * 16;
    const unsigned* pm0 = pm + (mrow + g)     * (LL / 32);
    const unsigned* pm1 = pm + (mrow + g + 8) * (LL / 32);
    int klrow = lane & 7, ktile = lane >> 3;
    int vkv = ((lane >> 3) & 1) * 8 + (lane & 7);
    int vd  = (lane >> 4) * 8;
    int sh0 = 2 * tg;

    for (int kt = 0; kt < 16; kt++) {
        int s = kt & 1;
        if (kt + 1 < 16) { prefetchKV(kt + 1, s ^ 1); CP_COMMIT(); CP_WAIT1(); }
        else             { CP_WAIT0(); }
        __syncthreads();
        uint4 m0 = *reinterpret_cast<const uint4*>(pm0 + kt * 4);
        uint4 m1 = *reinterpret_cast<const uint4*>(pm1 + kt * 4);
        if (!qLoaded) {
            qLoaded = true;
            #pragma unroll
            for (int tt = 0; tt < 4; tt++) {
                const __half* qp = smh + (w * 16 + g) * 72 + tt * 16 + 2 * tg;
                aQ[tt][0] = *reinterpret_cast<const unsigned*>(qp);
                aQ[tt][1] = *reinterpret_cast<const unsigned*>(qp + 8 * 72);
                aQ[tt][2] = *reinterpret_cast<const unsigned*>(qp + 8);
                aQ[tt][3] = *reinterpret_cast<const unsigned*>(qp + 8 * 72 + 8);
            }
        }
        uint32_t ko = 9216 + s * 18432, vo = ko + 9216;

        // S = Q K^T (log2 domain, fp16 accum -> packed half2 C-frags)
        unsigned pp[16][2];
        __half2 hs0 = __float2half2_rn(0.f), hs1 = __float2half2_rn(0.f);
        #pragma unroll
        for (int j = 0; j < 16; j++) {
            unsigned bq[2][4];
            uint32_t ka = base + ((j * 8 + klrow) * 72 + ktile * 8 + ko) * 2;
            ldsm_x4(bq[0], ka);
            ldsm_x4(bq[1], ka + 64);
            unsigned scp[2] = {0u, 0u};
            #pragma unroll
            for (int tt = 0; tt < 4; tt++)
                mma_f16h(scp, aQ[tt], bq[tt >> 1][(tt & 1) * 2], bq[tt >> 1][(tt & 1) * 2 + 1]);

            unsigned w0 = (&m0.x)[j >> 2];
            unsigned w1 = (&m1.x)[j >> 2];
            int sh = (j & 3) * 8 + sh0;
            unsigned f0 = (w0 >> sh) & 3u;
            unsigned f1 = (w1 >> sh) & 3u;
            unsigned km0 = ((f0 & 1u) ? 0u : 0x0000FFFFu) | ((f0 & 2u) ? 0u : 0xFFFF0000u);
            unsigned km1 = ((f1 & 1u) ? 0u : 0x0000FFFFu) | ((f1 & 2u) ? 0u : 0xFFFF0000u);
            unsigned p0 = ex2_f16x2(scp[0]) & km0;
            unsigned p1 = ex2_f16x2(scp[1]) & km1;
            pp[j][0] = p0;
            pp[j][1] = p1;
            hs0 = __hadd2(hs0, *reinterpret_cast<__half2*>(&p0));
            hs1 = __hadd2(hs1, *reinterpret_cast<__half2*>(&p1));
        }
        l0 += __low2float(hs0) + __high2float(hs0);
        l1 += __low2float(hs1) + __high2float(hs1);

        // O += P @ V (fp16 accum; pp rows are the A-fragments directly)
        #pragma unroll
        for (int tt = 0; tt < 8; tt++) {
            uint32_t va = base + ((tt * 16 + vkv) * 72 + vd + vo) * 2;
            #pragma unroll
            for (int njp = 0; njp < 4; njp++) {
                unsigned bv[4];
                ldsm_x4_t(bv, va + njp * 32);
                mma_f16h(O[2*njp    ], &pp[2*tt][0], bv[0], bv[1]);
                mma_f16h(O[2*njp + 1], &pp[2*tt][0], bv[2], bv[3]);
            }
        }
        __syncthreads();
    }

    l0 += __shfl_xor_sync(0xFFFFFFFFu, l0, 1);
    l0 += __shfl_xor_sync(0xFFFFFFFFu, l0, 2);
    l1 += __shfl_xor_sync(0xFFFFFFFFu, l1, 1);
    l1 += __shfl_xor_sync(0xFFFFFFFFu, l1, 2);
    float r0 = 1.f / l0, r1 = 1.f / l1;
    size_t orow = qrow0 + w * 16 + g;
    #pragma unroll
    for (int nj = 0; nj < 8; nj++) {
        int col = h * 64 + nj * 8 + 2 * tg;
        __half2 o0 = *reinterpret_cast<__half2*>(&O[nj][0]);
        __half2 o1 = *reinterpret_cast<__half2*>(&O[nj][1]);
        *reinterpret_cast<unsigned*>(g_attnh + orow * EN + col) =
            pack_f16(__low2float(o0) * r0, __high2float(o0) * r0);
        *reinterpret_cast<unsigned*>(g_attnh + (orow + 8) * EN + col) =
            pack_f16(__low2float(o1) * r1, __high2float(o1) * r1);
    }
}

// ---------------- launch -----------------------------------------------------
extern "C" void kernel_launch(void* const* d_in, const int* in_sizes, int n_in,
                              void* d_out, int out_size) {
    const float* x     = (const float*)d_in[0];
    const uint4* mask4 = (const uint4*)d_in[1];
    const float* ln1_s = (const float*)d_in[2];
    const float* ln1_b = (const float*)d_in[3];
    const float* Wqkv  = (const float*)d_in[4];
    const float* bqkv  = (const float*)d_in[5];
    const float* Wo    = (const float*)d_in[6];
    const float* bo    = (const float*)d_in[7];
    const float* ln2_s = (const float*)d_in[8];
    const float* ln2_b = (const float*)d_in[9];
    const float* lnf_s = (const float*)d_in[10];
    const float* lnf_b = (const float*)d_in[11];
    const float* W1    = (const float*)d_in[12];
    const float* b1    = (const float*)d_in[13];
    const float* W2    = (const float*)d_in[14];
    const float* b2    = (const float*)d_in[15];
    float* out = (float*)d_out;

    __half *p_hh, *p_qkvh, *p_attnh, *p_h2, *p_ff, *p_Wqkvt, *p_Wot, *p_W1t, *p_W2t;
    float *p_x1, *p_bqkv;
    unsigned* p_pmask;
    cudaGetSymbolAddress((void**)&p_hh,    g_hh);
    cudaGetSymbolAddress((void**)&p_qkvh,  g_qkvh);
    cudaGetSymbolAddress((void**)&p_attnh, g_attnh);
    cudaGetSymbolAddress((void**)&p_x1,    g_x1);
    cudaGetSymbolAddress((void**)&p_h2,    g_h2);
    cudaGetSymbolAddress((void**)&p_ff,    g_ff);
    cudaGetSymbolAddress((void**)&p_bqkv,  g_bqkv);
    cudaGetSymbolAddress((void**)&p_pmask, g_pmask);
    cudaGetSymbolAddress((void**)&p_Wqkvt, g_Wqkvt);
    cudaGetSymbolAddress((void**)&p_Wot,   g_Wot);
    cudaGetSymbolAddress((void**)&p_W1t,   g_W1t);
    cudaGetSymbolAddress((void**)&p_W2t,   g_W2t);

    cudaFuncSetAttribute(gemm4_k<EPI_BIAS, __half>, cudaFuncAttributeMaxDynamicSharedMemorySize, GEMM_SMEM);
    cudaFuncSetAttribute(gemm4_k<EPI_RES,  float>,  cudaFuncAttributeMaxDynamicSharedMemorySize, GEMM_SMEM);
    cudaFuncSetAttribute(gemm4_k<EPI_GELU, __half>, cudaFuncAttributeMaxDynamicSharedMemorySize, GEMM_SMEM);
    cudaFuncSetAttribute(attn_k, cudaFuncAttributeMaxDynamicSharedMemorySize, ATTN_SMEM);

    static cudaStream_t s2 = nullptr;
    static cudaEvent_t evF = nullptr, evJ = nullptr;
    if (!s2) {
        cudaStreamCreateWithFlags(&s2, cudaStreamNonBlocking);
        cudaEventCreateWithFlags(&evF, cudaEventDisableTiming);
        cudaEventCreateWithFlags(&evJ, cudaEventDisableTiming);
    }

    // fork: mask bit-pack runs on s2, overlapping transT/LN1/QKV GEMM
    cudaEventRecord(evF, 0);
    cudaStreamWaitEvent(s2, evF, 0);
    maskpack_k<<<PMW / 256, 256, 0, s2>>>(mask4, p_pmask);
    cudaEventRecord(evJ, s2);

    dim3 tb(256);
    transT_f16_k<<<dim3(3*EN/64, EN/64), tb>>>(Wqkv, p_Wqkvt, EN, 3*EN, EN, QSCALE);
    transT_f16_k<<<dim3(EN/64,   EN/64), tb>>>(Wo,   p_Wot,   EN, EN,   0, 1.f);
    transT_f16_k<<<dim3(DFFN/64, EN/64), tb>>>(W1,   p_W1t,   EN, DFFN, 0, 1.f);
    transT_f16_k<<<dim3(EN/64, DFFN/64), tb>>>(W2,   p_W2t,   DFFN, EN, 0, 1.f);
    scale_bias_k<<<3*EN/256, 256>>>(bqkv, p_bqkv);

    // 1. h = LN1(x) -> fp16
    ln1_k<<<ROWS, 256>>>(x, ln1_s, ln1_b, p_hh);
    // 2. qkv = h @ Wqkv + bqkv (fp16 out; q pre-scaled to log2 domain)
    gemm4_k<EPI_BIAS, __half><<<dim3(3*EN/128, ROWS/128), 128, GEMM_SMEM>>>(
        ROWS, 3*EN, EN, p_hh, p_Wqkvt, p_bqkv, nullptr, p_qkvh);

    // join: packed mask must be ready before attention
    cudaStreamWaitEvent(0, evJ, 0);
    // 3. attention
    attn_k<<<dim3(LL/128, NB*HHH), 256, ATTN_SMEM>>>(p_pmask, p_qkvh);
    // 4. x1 = x + attn @ Wo + bo
    gemm4_k<EPI_RES, float><<<dim3(EN/128, ROWS/128), 128, GEMM_SMEM>>>(
        ROWS, EN, EN, p_attnh, p_Wot, bo, x, p_x1);
    // 5. h2 = LNf(LN2(x1)) -> fp16
    ln2f_k<<<ROWS, 256>>>(p_x1, ln2_s, ln2_b, lnf_s, lnf_b, p_h2);
    // 6. ff = gelu(h2 @ W1 + b1)
    gemm4_k<EPI_GELU, __half><<<dim3(DFFN/128, ROWS/128), 128, GEMM_SMEM>>>(
        ROWS, DFFN, EN, p_h2, p_W1t, b1, nullptr, p_ff);
    // 7. out = x1 + ff @ W2 + b2
    gemm4_k<EPI_RES, float><<<dim3(EN/128, ROWS/128), 128, GEMM_SMEM>>>(
        ROWS, EN, DFFN, p_ff, p_W2t, b2, p_x1, out);
}

// round 16
// speedup vs baseline: 1.6621x; 1.0121x over previous
#include <cuda_runtime.h>
#include <cuda_fp16.h>
#include <cstdint>

#define EN   1024
#define DFFN 4096
#define NB   2
#define LL   2048
#define HHH  16
#define ROWS (NB*LL)   // 4096
#define PMW  (NB*HHH*LL*LL/32)   // packed mask words: 4194304
#define QSCALE 0.18033688011112042f   // log2(e) / 8

// ---------------- scratch (device globals; no allocation allowed) ----------
__device__ __half g_hh   [ROWS*EN];
__device__ __half g_qkvh [ROWS*3*EN];
__device__ __half g_attnh[ROWS*EN];
__device__ float  g_x1   [ROWS*EN];
__device__ __half g_h2   [ROWS*EN];
__device__ __half g_ff   [ROWS*DFFN];
__device__ float  g_bqkv [3*EN];
__device__ unsigned g_pmask[PMW];
__device__ __half g_Wqkvt[3*EN*EN];
__device__ __half g_Wot  [EN*EN];
__device__ __half g_W1t  [DFFN*EN];
__device__ __half g_W2t  [EN*DFFN];

// ---------------- helpers ---------------------------------------------------
__device__ __forceinline__ unsigned pack_f16(float lo, float hi) {
    __half2 p = __floats2half2_rn(lo, hi);
    return *reinterpret_cast<unsigned*>(&p);
}
__device__ __forceinline__ void mma_f16(float* c, const unsigned* a, unsigned b0, unsigned b1) {
    asm volatile(
        "mma.sync.aligned.m16n8k16.row.col.f32.f16.f16.f32 "
        "{%0,%1,%2,%3},{%4,%5,%6,%7},{%8,%9},{%0,%1,%2,%3};"
        : "+f"(c[0]), "+f"(c[1]), "+f"(c[2]), "+f"(c[3])
        : "r"(a[0]), "r"(a[1]), "r"(a[2]), "r"(a[3]), "r"(b0), "r"(b1));
}
// fp16-accumulate variant: C is 2 regs (packed half2 per 8-row group)
__device__ __forceinline__ void mma_f16h(unsigned* c, const unsigned* a, unsigned b0, unsigned b1) {
    asm volatile(
        "mma.sync.aligned.m16n8k16.row.col.f16.f16.f16.f16 "
        "{%0,%1},{%2,%3,%4,%5},{%6,%7},{%0,%1};"
        : "+r"(c[0]), "+r"(c[1])
        : "r"(a[0]), "r"(a[1]), "r"(a[2]), "r"(a[3]), "r"(b0), "r"(b1));
}
__device__ __forceinline__ void cpa16(unsigned dst, const void* src) {
    asm volatile("cp.async.cg.shared.global [%0], [%1], 16;\n" :: "r"(dst), "l"(src));
}
#define CP_COMMIT() asm volatile("cp.async.commit_group;\n" ::)
#define CP_WAIT0()  asm volatile("cp.async.wait_group 0;\n" ::)
#define CP_WAIT1()  asm volatile("cp.async.wait_group 1;\n" ::)

__device__ __forceinline__ uint32_t smem_u32(const void* p) {
    uint32_t a;
    asm("{ .reg .u64 t; cvta.to.shared.u64 t, %1; cvt.u32.u64 %0, t; }" : "=r"(a) : "l"(p));
    return a;
}
__device__ __forceinline__ void ldsm_x4(unsigned* r, uint32_t addr) {
    asm volatile("ldmatrix.sync.aligned.m8n8.x4.shared.b16 {%0,%1,%2,%3}, [%4];"
        : "=r"(r[0]), "=r"(r[1]), "=r"(r[2]), "=r"(r[3]) : "r"(addr));
}
__device__ __forceinline__ void ldsm_x4_t(unsigned* r, uint32_t addr) {
    asm volatile("ldmatrix.sync.aligned.m8n8.x4.trans.shared.b16 {%0,%1,%2,%3}, [%4];"
        : "=r"(r[0]), "=r"(r[1]), "=r"(r[2]), "=r"(r[3]) : "r"(addr));
}
__device__ __forceinline__ unsigned ex2_f16x2(unsigned x) {
    unsigned r;
    asm("ex2.approx.f16x2 %0, %1;" : "=r"(r) : "r"(x));
    return r;
}

__device__ __forceinline__ void blockReduce2(float& a, float& b) {
    __shared__ float sm[16];
    #pragma unroll
    for (int o = 16; o; o >>= 1) {
        a += __shfl_xor_sync(0xFFFFFFFFu, a, o);
        b += __shfl_xor_sync(0xFFFFFFFFu, b, o);
    }
    int w = threadIdx.x >> 5, lane = threadIdx.x & 31;
    __syncthreads();
    if (lane == 0) { sm[w] = a; sm[8 + w] = b; }
    __syncthreads();
    a = 0.f; b = 0.f;
    #pragma unroll
    for (int i = 0; i < 8; i++) { a += sm[i]; b += sm[8 + i]; }
}

// ---------------- mask bit-pack ----------------------------------------------
__global__ __launch_bounds__(256) void maskpack_k(const uint4* __restrict__ in,
                                                  unsigned* __restrict__ out) {
    int o = blockIdx.x * 256 + threadIdx.x;
    const uint4* p = in + (size_t)o * 8;
    unsigned m = 0;
    #pragma unroll
    for (int i = 0; i < 8; i++) {
        uint4 v = p[i];
        m |= (v.x ? 1u : 0u) << (i * 4 + 0);
        m |= (v.y ? 1u : 0u) << (i * 4 + 1);
        m |= (v.z ? 1u : 0u) << (i * 4 + 2);
        m |= (v.w ? 1u : 0u) << (i * 4 + 3);
    }
    out[o] = m;
}

// ---------------- pre-pass kernels -------------------------------------------
__global__ __launch_bounds__(256) void transT_f16_k(const float* __restrict__ in,
                                                    __half* __restrict__ out,
                                                    int K, int N, int slim, float sc) {
    __shared__ float tile[64][65];
    int k0 = blockIdx.y * 64, n0 = blockIdx.x * 64;
    int tx = threadIdx.x & 63, ty = threadIdx.x >> 6;
    #pragma unroll
    for (int i = 0; i < 64; i += 4)
        tile[ty + i][tx] = in[(size_t)(k0 + ty + i) * N + n0 + tx];
    __syncthreads();
    #pragma unroll
    for (int i = 0; i < 64; i += 4) {
        int n = n0 + ty + i;
        float v = tile[tx][ty + i];
        out[(size_t)n * K + k0 + tx] = __float2half(n < slim ? v * sc : v);
    }
}
__global__ __launch_bounds__(256) void scale_bias_k(const float* __restrict__ in,
                                                    float* __restrict__ out) {
    int i = blockIdx.x * 256 + threadIdx.x;
    out[i] = i < EN ? in[i] * QSCALE : in[i];
}

// ---------------- LN kernels -------------------------------------------------
__global__ __launch_bounds__(256) void ln1_k(const float* __restrict__ x,
                                             const float* __restrict__ s,
                                             const float* __restrict__ b,
                                             __half* __restrict__ out) {
    int row = blockIdx.x, t = threadIdx.x;
    float4 v = reinterpret_cast<const float4*>(x + (size_t)row * EN)[t];
    float sum = v.x + v.y + v.z + v.w;
    float sq  = v.x*v.x + v.y*v.y + v.z*v.z + v.w*v.w;
    blockReduce2(sum, sq);
    float mu = sum * (1.f / EN);
    float rs = rsqrtf(sq * (1.f / EN) - mu * mu + 1e-5f);
    float4 sv = reinterpret_cast<const float4*>(s)[t];
    float4 bv = reinterpret_cast<const float4*>(b)[t];
    uint2 pk;
    pk.x = pack_f16((v.x - mu) * rs * sv.x + bv.x, (v.y - mu) * rs * sv.y + bv.y);
    pk.y = pack_f16((v.z - mu) * rs * sv.z + bv.z, (v.w - mu) * rs * sv.w + bv.w);
    reinterpret_cast<uint2*>(out + (size_t)row * EN)[t] = pk;
}

__global__ __launch_bounds__(256) void ln2f_k(const float* __restrict__ x,
                                              const float* __restrict__ s2,
                                              const float* __restrict__ b2,
                                              const float* __restrict__ sf,
                                              const float* __restrict__ bf,
                                              __half* __restrict__ out) {
    int row = blockIdx.x, t = threadIdx.x;
    float4 v = reinterpret_cast<const float4*>(x + (size_t)row * EN)[t];
    float sum = v.x + v.y + v.z + v.w;
    float sq  = v.x*v.x + v.y*v.y + v.z*v.z + v.w*v.w;
    blockReduce2(sum, sq);
    float mu = sum * (1.f / EN);
    float rs = rsqrtf(sq * (1.f / EN) - mu * mu + 1e-5f);
    float4 sv = reinterpret_cast<const float4*>(s2)[t];
    float4 bv = reinterpret_cast<const float4*>(b2)[t];
    float4 y;
    y.x = (v.x - mu) * rs * sv.x + bv.x;
    y.y = (v.y - mu) * rs * sv.y + bv.y;
    y.z = (v.z - mu) * rs * sv.z + bv.z;
    y.w = (v.w - mu) * rs * sv.w + bv.w;
    float sum2 = y.x + y.y + y.z + y.w;
    float sq2  = y.x*y.x + y.y*y.y + y.z*y.z + y.w*y.w;
    blockReduce2(sum2, sq2);
    float mu2 = sum2 * (1.f / EN);
    float rs2 = rsqrtf(sq2 * (1.f / EN) - mu2 * mu2 + 1e-5f);
    float4 fv = reinterpret_cast<const float4*>(sf)[t];
    float4 gv = reinterpret_cast<const float4*>(bf)[t];
    uint2 pk;
    pk.x = pack_f16((y.x - mu2) * rs2 * fv.x + gv.x, (y.y - mu2) * rs2 * fv.y + gv.y);
    pk.y = pack_f16((y.z - mu2) * rs2 * fv.z + gv.z, (y.w - mu2) * rs2 * fv.w + gv.w);
    reinterpret_cast<uint2*>(out + (size_t)row * EN)[t] = pk;
}

// ---------------- fp16 GEMM (128x128, 2 CTA/SM; HACC = fp16 accumulate) ------
#define EPI_BIAS 0
#define EPI_GELU 1
#define EPI_RES  2

#define STG_WORDS (2*128*48)
#define GEMM_SMEM (2*STG_WORDS*4)

template <int EPI, typename TO, int HACC>
__global__ __launch_bounds__(128, 2) void gemm4_k(int M, int N, int K,
                                                  const __half* __restrict__ A,
                                                  const __half* __restrict__ Bt,
                                                  const float* __restrict__ bias,
                                                  const float* __restrict__ res,
                                                  TO* __restrict__ C) {
    extern __shared__ float smem[];
    constexpr int BKE = 64;
    int bm = blockIdx.y * 128, bn = blockIdx.x * 128;
    int t = threadIdx.x, wid = t >> 5, lane = t & 31;
    int g = lane >> 2, tg = lane & 3;
    int wr = (wid & 1) * 64;
    int wc = (wid >> 1) * 64;

    float    cf[4][8][4];
    unsigned ch[4][8][2];
    #pragma unroll
    for (int mi = 0; mi < 4; mi++)
        #pragma unroll
        for (int nj = 0; nj < 8; nj++) {
            if constexpr (HACC) { ch[mi][nj][0] = 0u; ch[mi][nj][1] = 0u; }
            else {
                #pragma unroll
                for (int q = 0; q < 4; q++) cf[mi][nj][q] = 0.f;
            }
        }

    const __half* Ab = A  + (size_t)bm * K;
    const __half* Bb = Bt + (size_t)bn * K;
    int r8 = t >> 3, c8 = t & 7;

    auto prefetch = [&](int kt, int s) {
        float* dA = smem + s * STG_WORDS;
        float* dB = dA + 128 * 48;
        size_t kofs = (size_t)kt * BKE + c8 * 8;
        unsigned da = (unsigned)__cvta_generic_to_shared(dA + r8 * 48 + c8 * 4);
        unsigned db = (unsigned)__cvta_generic_to_shared(dB + r8 * 48 + c8 * 4);
        #pragma unroll
        for (int i = 0; i < 8; i++) {
            cpa16(da + i * 16 * 48 * 4, Ab + (size_t)(r8 + i * 16) * K + kofs);
            cpa16(db + i * 16 * 48 * 4, Bb + (size_t)(r8 + i * 16) * K + kofs);
        }
    };

    int Tn = K / BKE;
    prefetch(0, 0);
    CP_COMMIT();

    for (int kt = 0; kt < Tn; kt++) {
        int s = kt & 1;
        CP_WAIT0();
        __syncthreads();
        if (kt + 1 < Tn) { prefetch(kt + 1, s ^ 1); CP_COMMIT(); }

        const float* cA = smem + s * STG_WORDS;
        const float* cB = cA + 128 * 48;
        #pragma unroll
        for (int u = 0; u < 2; u++) {
            uint4 aF[8], bF[8];
            #pragma unroll
            for (int i = 0; i < 8; i++) {
                int r = wr + (i >> 1) * 16 + g + (i & 1) * 8;
                aF[i] = *reinterpret_cast<const uint4*>(cA + r * 48 + u * 16 + tg * 4);
            }
            #pragma unroll
            for (int nj = 0; nj < 8; nj++) {
                int cc = wc + nj * 8 + g;
                bF[nj] = *reinterpret_cast<const uint4*>(cB + cc * 48 + u * 16 + tg * 4);
            }
            #pragma unroll
            for (int mi = 0; mi < 4; mi++) {
                unsigned ae[4] = {aF[2*mi].x, aF[2*mi+1].x, aF[2*mi].y, aF[2*mi+1].y};
                unsigned ao[4] = {aF[2*mi].z, aF[2*mi+1].z, aF[2*mi].w, aF[2*mi+1].w};
                #pragma unroll
                for (int nj = 0; nj < 8; nj++) {
                    if constexpr (HACC) {
                        mma_f16h(ch[mi][nj], ae, bF[nj].x, bF[nj].y);
                        mma_f16h(ch[mi][nj], ao, bF[nj].z, bF[nj].w);
                    } else {
                        mma_f16(cf[mi][nj], ae, bF[nj].x, bF[nj].y);
                        mma_f16(cf[mi][nj], ao, bF[nj].z, bF[nj].w);
                    }
                }
            }
        }
    }

    #pragma unroll
    for (int mi = 0; mi < 4; mi++) {
        #pragma unroll
        for (int nj = 0; nj < 8; nj++) {
            int row = bm + wr + mi * 16 + g;
            int col = bn + wc + nj * 8 + tg * 2;
            float b0 = bias[col], b1 = bias[col + 1];
            float v0, v1, v2, v3;
            if constexpr (HACC) {
                __half2 h0 = *reinterpret_cast<__half2*>(&ch[mi][nj][0]);
                __half2 h1 = *reinterpret_cast<__half2*>(&ch[mi][nj][1]);
                v0 = __low2float(h0); v1 = __high2float(h0);
                v2 = __low2float(h1); v3 = __high2float(h1);
            } else {
                v0 = cf[mi][nj][0]; v1 = cf[mi][nj][1];
                v2 = cf[mi][nj][2]; v3 = cf[mi][nj][3];
            }
            v0 += b0; v1 += b1; v2 += b0; v3 += b1;
            if (EPI == EPI_GELU) {
                v0 = 0.5f * v0 * (1.f + erff(v0 * 0.70710678118f));
                v1 = 0.5f * v1 * (1.f + erff(v1 * 0.70710678118f));
                v2 = 0.5f * v2 * (1.f + erff(v2 * 0.70710678118f));
                v3 = 0.5f * v3 * (1.f + erff(v3 * 0.70710678118f));
            }
            if (EPI == EPI_RES) {
                float2 r0 = *reinterpret_cast<const float2*>(res + (size_t)row * N + col);
                float2 r1 = *reinterpret_cast<const float2*>(res + (size_t)(row + 8) * N + col);
                v0 += r0.x; v1 += r0.y; v2 += r1.x; v3 += r1.y;
            }
            if (sizeof(TO) == 4) {
                float* Cf = (float*)C;
                *reinterpret_cast<float2*>(Cf + (size_t)row * N + col)       = make_float2(v0, v1);
                *reinterpret_cast<float2*>(Cf + (size_t)(row + 8) * N + col) = make_float2(v2, v3);
            } else {
                __half* Ch = (__half*)C;
                *reinterpret_cast<unsigned*>(Ch + (size_t)row * N + col)       = pack_f16(v0, v1);
                *reinterpret_cast<unsigned*>(Ch + (size_t)(row + 8) * N + col) = pack_f16(v2, v3);
            }
        }
    }
}

// ---------------- fp16 flash attention: fp16-accum MMA + packed ex2 ----------
#define ATTN_SMEM ((9216 + 2*18432)*2)   // 92160 B

__global__ __launch_bounds__(256) void attn_k(const unsigned* __restrict__ pm,
                                              const __half* __restrict__ qkv) {
    extern __shared__ __half smh[];
    uint32_t base = smem_u32(smh);
    int t = threadIdx.x, w = t >> 5, lane = t & 31;
    int g = lane >> 2, tg = lane & 3;
    int qt = blockIdx.x, nh = blockIdx.y;
    int n = nh >> 4, h = nh & 15;
    size_t qrow0 = (size_t)n * LL + (size_t)qt * 128;
    int r8 = t >> 3, c8 = t & 7;

    #pragma unroll
    for (int i = 0; i < 4; i++) {
        int r = r8 + i * 32;
        cpa16(base + (r * 72 + c8 * 8) * 2,
              qkv + (qrow0 + r) * 3072 + h * 64 + c8 * 8);
    }
    auto prefetchKV = [&](int kt, int s) {
        uint32_t ko = 9216 + s * 18432, vo = ko + 9216;
        size_t rowb = ((size_t)n * LL + kt * 128 + r8) * 3072 + h * 64 + c8 * 8;
        #pragma unroll
        for (int i = 0; i < 4; i++) {
            cpa16(base + (ko + (r8 + i * 32) * 72 + c8 * 8) * 2,
                  qkv + rowb + (size_t)i * 32 * 3072 + 1024);
            cpa16(base + (vo + (r8 + i * 32) * 72 + c8 * 8) * 2,
                  qkv + rowb + (size_t)i * 32 * 3072 + 2048);
        }
    };
    prefetchKV(0, 0);
    CP_COMMIT();

    unsigned O[8][2];
    #pragma unroll
    for (int nj = 0; nj < 8; nj++) { O[nj][0] = 0u; O[nj][1] = 0u; }
    float l0 = 0.f, l1 = 0.f;
    unsigned aQ[4][4];
    bool qLoaded = false;

    size_t mrow = (size_t)nh * LL + (size_t)qt * 128 + w * 16;
    const unsigned* pm0 = pm + (mrow + g)     * (LL / 32);
    const unsigned* pm1 = pm + (mrow + g + 8) * (LL / 32);
    int klrow = lane & 7, ktile = lane >> 3;
    int vkv = ((lane >> 3) & 1) * 8 + (lane & 7);
    int vd  = (lane >> 4) * 8;
    int sh0 = 2 * tg;

    for (int kt = 0; kt < 16; kt++) {
        int s = kt & 1;
        if (kt + 1 < 16) { prefetchKV(kt + 1, s ^ 1); CP_COMMIT(); CP_WAIT1(); }
        else             { CP_WAIT0(); }
        __syncthreads();
        uint4 m0 = *reinterpret_cast<const uint4*>(pm0 + kt * 4);
        uint4 m1 = *reinterpret_cast<const uint4*>(pm1 + kt * 4);
        if (!qLoaded) {
            qLoaded = true;
            #pragma unroll
            for (int tt = 0; tt < 4; tt++) {
                const __half* qp = smh + (w * 16 + g) * 72 + tt * 16 + 2 * tg;
                aQ[tt][0] = *reinterpret_cast<const unsigned*>(qp);
                aQ[tt][1] = *reinterpret_cast<const unsigned*>(qp + 8 * 72);
                aQ[tt][2] = *reinterpret_cast<const unsigned*>(qp + 8);
                aQ[tt][3] = *reinterpret_cast<const unsigned*>(qp + 8 * 72 + 8);
            }
        }
        uint32_t ko = 9216 + s * 18432, vo = ko + 9216;

        unsigned pp[16][2];
        __half2 hs0 = __float2half2_rn(0.f), hs1 = __float2half2_rn(0.f);
        #pragma unroll
        for (int j = 0; j < 16; j++) {
            unsigned bq[2][4];
            uint32_t ka = base + ((j * 8 + klrow) * 72 + ktile * 8 + ko) * 2;
            ldsm_x4(bq[0], ka);
            ldsm_x4(bq[1], ka + 64);
            unsigned scp[2] = {0u, 0u};
            #pragma unroll
            for (int tt = 0; tt < 4; tt++)
                mma_f16h(scp, aQ[tt], bq[tt >> 1][(tt & 1) * 2], bq[tt >> 1][(tt & 1) * 2 + 1]);

            unsigned w0 = (&m0.x)[j >> 2];
            unsigned w1 = (&m1.x)[j >> 2];
            int sh = (j & 3) * 8 + sh0;
            unsigned f0 = (w0 >> sh) & 3u;
            unsigned f1 = (w1 >> sh) & 3u;
            unsigned km0 = ((f0 & 1u) ? 0u : 0x0000FFFFu) | ((f0 & 2u) ? 0u : 0xFFFF0000u);
            unsigned km1 = ((f1 & 1u) ? 0u : 0x0000FFFFu) | ((f1 & 2u) ? 0u : 0xFFFF0000u);
            unsigned p0 = ex2_f16x2(scp[0]) & km0;
            unsigned p1 = ex2_f16x2(scp[1]) & km1;
            pp[j][0] = p0;
            pp[j][1] = p1;
            hs0 = __hadd2(hs0, *reinterpret_cast<__half2*>(&p0));
            hs1 = __hadd2(hs1, *reinterpret_cast<__half2*>(&p1));
        }
        l0 += __low2float(hs0) + __high2float(hs0);
        l1 += __low2float(hs1) + __high2float(hs1);

        #pragma unroll
        for (int tt = 0; tt < 8; tt++) {
            uint32_t va = base + ((tt * 16 + vkv) * 72 + vd + vo) * 2;
            #pragma unroll
            for (int njp = 0; njp < 4; njp++) {
                unsigned bv[4];
                ldsm_x4_t(bv, va + njp * 32);
                mma_f16h(O[2*njp    ], &pp[2*tt][0], bv[0], bv[1]);
                mma_f16h(O[2*njp + 1], &pp[2*tt][0], bv[2], bv[3]);
            }
        }
        __syncthreads();
    }

    l0 += __shfl_xor_sync(0xFFFFFFFFu, l0, 1);
    l0 += __shfl_xor_sync(0xFFFFFFFFu, l0, 2);
    l1 += __shfl_xor_sync(0xFFFFFFFFu, l1, 1);
    l1 += __shfl_xor_sync(0xFFFFFFFFu, l1, 2);
    float r0 = 1.f / l0, r1 = 1.f / l1;
    size_t orow = qrow0 + w * 16 + g;
    #pragma unroll
    for (int nj = 0; nj < 8; nj++) {
        int col = h * 64 + nj * 8 + 2 * tg;
        __half2 o0 = *reinterpret_cast<__half2*>(&O[nj][0]);
        __half2 o1 = *reinterpret_cast<__half2*>(&O[nj][1]);
        *reinterpret_cast<unsigned*>(g_attnh + orow * EN + col) =
            pack_f16(__low2float(o0) * r0, __high2float(o0) * r0);
        *reinterpret_cast<unsigned*>(g_attnh + (orow + 8) * EN + col) =
            pack_f16(__low2float(o1) * r1, __high2float(o1) * r1);
    }
}

// ---------------- launch -----------------------------------------------------
extern "C" void kernel_launch(void* const* d_in, const int* in_sizes, int n_in,
                              void* d_out, int out_size) {
    const float* x     = (const float*)d_in[0];
    const uint4* mask4 = (const uint4*)d_in[1];
    const float* ln1_s = (const float*)d_in[2];
    const float* ln1_b = (const float*)d_in[3];
    const float* Wqkv  = (const float*)d_in[4];
    const float* bqkv  = (const float*)d_in[5];
    const float* Wo    = (const float*)d_in[6];
    const float* bo    = (const float*)d_in[7];
    const float* ln2_s = (const float*)d_in[8];
    const float* ln2_b = (const float*)d_in[9];
    const float* lnf_s = (const float*)d_in[10];
    const float* lnf_b = (const float*)d_in[11];
    const float* W1    = (const float*)d_in[12];
    const float* b1    = (const float*)d_in[13];
    const float* W2    = (const float*)d_in[14];
    const float* b2    = (const float*)d_in[15];
    float* out = (float*)d_out;

    __half *p_hh, *p_qkvh, *p_attnh, *p_h2, *p_ff, *p_Wqkvt, *p_Wot, *p_W1t, *p_W2t;
    float *p_x1, *p_bqkv;
    unsigned* p_pmask;
    cudaGetSymbolAddress((void**)&p_hh,    g_hh);
    cudaGetSymbolAddress((void**)&p_qkvh,  g_qkvh);
    cudaGetSymbolAddress((void**)&p_attnh, g_attnh);
    cudaGetSymbolAddress((void**)&p_x1,    g_x1);
    cudaGetSymbolAddress((void**)&p_h2,    g_h2);
    cudaGetSymbolAddress((void**)&p_ff,    g_ff);
    cudaGetSymbolAddress((void**)&p_bqkv,  g_bqkv);
    cudaGetSymbolAddress((void**)&p_pmask, g_pmask);
    cudaGetSymbolAddress((void**)&p_Wqkvt, g_Wqkvt);
    cudaGetSymbolAddress((void**)&p_Wot,   g_Wot);
    cudaGetSymbolAddress((void**)&p_W1t,   g_W1t);
    cudaGetSymbolAddress((void**)&p_W2t,   g_W2t);

    cudaFuncSetAttribute(gemm4_k<EPI_BIAS, __half, 1>, cudaFuncAttributeMaxDynamicSharedMemorySize, GEMM_SMEM);
    cudaFuncSetAttribute(gemm4_k<EPI_RES,  float, 1>,  cudaFuncAttributeMaxDynamicSharedMemorySize, GEMM_SMEM);
    cudaFuncSetAttribute(gemm4_k<EPI_GELU, __half, 0>, cudaFuncAttributeMaxDynamicSharedMemorySize, GEMM_SMEM);
    cudaFuncSetAttribute(gemm4_k<EPI_RES,  float, 0>,  cudaFuncAttributeMaxDynamicSharedMemorySize, GEMM_SMEM);
    cudaFuncSetAttribute(attn_k, cudaFuncAttributeMaxDynamicSharedMemorySize, ATTN_SMEM);

    static cudaStream_t s2 = nullptr;
    static cudaEvent_t evF = nullptr, evJ = nullptr;
    if (!s2) {
        cudaStreamCreateWithFlags(&s2, cudaStreamNonBlocking);
        cudaEventCreateWithFlags(&evF, cudaEventDisableTiming);
        cudaEventCreateWithFlags(&evJ, cudaEventDisableTiming);
    }

    // fork: mask bit-pack runs on s2, overlapping transT/LN1/QKV GEMM
    cudaEventRecord(evF, 0);
    cudaStreamWaitEvent(s2, evF, 0);
    maskpack_k<<<PMW / 256, 256, 0, s2>>>(mask4, p_pmask);
    cudaEventRecord(evJ, s2);

    dim3 tb(256);
    transT_f16_k<<<dim3(3*EN/64, EN/64), tb>>>(Wqkv, p_Wqkvt, EN, 3*EN, EN, QSCALE);
    transT_f16_k<<<dim3(EN/64,   EN/64), tb>>>(Wo,   p_Wot,   EN, EN,   0, 1.f);
    transT_f16_k<<<dim3(DFFN/64, EN/64), tb>>>(W1,   p_W1t,   EN, DFFN, 0, 1.f);
    transT_f16_k<<<dim3(EN/64, DFFN/64), tb>>>(W2,   p_W2t,   DFFN, EN, 0, 1.f);
    scale_bias_k<<<3*EN/256, 256>>>(bqkv, p_bqkv);

    // 1. h = LN1(x) -> fp16
    ln1_k<<<ROWS, 256>>>(x, ln1_s, ln1_b, p_hh);
    // 2. qkv = h @ Wqkv + bqkv (fp16 accumulate)
    gemm4_k<EPI_BIAS, __half, 1><<<dim3(3*EN/128, ROWS/128), 128, GEMM_SMEM>>>(
        ROWS, 3*EN, EN, p_hh, p_Wqkvt, p_bqkv, nullptr, p_qkvh);

    // join: packed mask must be ready before attention
    cudaStreamWaitEvent(0, evJ, 0);
    // 3. attention
    attn_k<<<dim3(LL/128, NB*HHH), 256, ATTN_SMEM>>>(p_pmask, p_qkvh);
    // 4. x1 = x + attn @ Wo + bo (fp16 accumulate)
    gemm4_k<EPI_RES, float, 1><<<dim3(EN/128, ROWS/128), 128, GEMM_SMEM>>>(
        ROWS, EN, EN, p_attnh, p_Wot, bo, x, p_x1);
    // 5. h2 = LNf(LN2(x1)) -> fp16
    ln2f_k<<<ROWS, 256>>>(p_x1, ln2_s, ln2_b, lnf_s, lnf_b, p_h2);
    // 6. ff = gelu(h2 @ W1 + b1) (fp32 accumulate)
    gemm4_k<EPI_GELU, __half, 0><<<dim3(DFFN/128, ROWS/128), 128, GEMM_SMEM>>>(
        ROWS, DFFN, EN, p_h2, p_W1t, b1, nullptr, p_ff);
    // 7. out = x1 + ff @ W2 + b2 (fp32 accumulate)
    gemm4_k<EPI_RES, float, 0><<<dim3(EN/128, ROWS/128), 128, GEMM_SMEM>>>(
        ROWS, EN, DFFN, p_ff, p_W2t, b2, p_x1, out);
}